// round 1
// baseline (speedup 1.0000x reference)
#include <cuda_runtime.h>
#include <math.h>

#define NN 50000
#define EE 800000
#define D0 128
#define D1 128
#define D2 64
#define CLS 128

// ---------------- scratch (static device allocations only) ----------------
__device__ float g_h0[NN * D0];
__device__ float g_t0[NN * D1];   // reused (layer1 needs only NN*64)
__device__ float g_t1[NN * D1];
__device__ float g_a0[NN * D1];
__device__ float g_a1[NN * D1];
__device__ float g_h1[NN * D1];
__device__ float g_res[NN * D2];
__device__ float g_h2[NN * D2];
__device__ float g_wc[4 * 128 * 128]; // combined weights
__device__ int   g_is64;

// ---------------- helpers ----------------
__device__ __forceinline__ void red_add_v4(float* p, float a, float b, float c, float d) {
    asm volatile("red.global.add.v4.f32 [%0], {%1,%2,%3,%4};"
                 :: "l"(p), "f"(a), "f"(b), "f"(c), "f"(d) : "memory");
}
__device__ __forceinline__ void red_add_v2(float* p, float a, float b) {
    asm volatile("red.global.add.v2.f32 [%0], {%1,%2};"
                 :: "l"(p), "f"(a), "f"(b) : "memory");
}

// ---------------- tiny kernels ----------------
__global__ void detect_kernel(const int* __restrict__ ei) {
    if (threadIdx.x == 0 && blockIdx.x == 0) {
        int z = 0;
        for (int i = 1; i < 129; i += 2) z |= ei[i];
        g_is64 = (z == 0) ? 1 : 0;
    }
}

__global__ void pe_kernel(const float* __restrict__ x, const float* __restrict__ pe,
                          float* __restrict__ h0, int total) {
    int idx = blockIdx.x * blockDim.x + threadIdx.x;
    if (idx < total) h0[idx] = x[idx] + pe[idx & 127];
}

__global__ void addw_kernel(const float* __restrict__ a, const float* __restrict__ b,
                            float* __restrict__ c, int n) {
    int i = blockIdx.x * blockDim.x + threadIdx.x;
    if (i < n) c[i] = a[i] + b[i];
}

__global__ void zero_kernel(float* __restrict__ p, int n) {
    for (int i = blockIdx.x * blockDim.x + threadIdx.x; i < n; i += gridDim.x * blockDim.x)
        p[i] = 0.f;
}

// ---------------- GEMM: out[n][j] = sum_k H[n][k]*W[k][j] (+bias) ----------------
// 4x4 register tile per thread. Rows tile in shared (broadcast LDS), W via L1-cached LDG.128.
template<int DIN, int DOUT>
__global__ __launch_bounds__(256) void gemm_kernel(
    const float* __restrict__ H, const float* __restrict__ W,
    const float* __restrict__ bias, float* __restrict__ out, int nrows)
{
    constexpr int TCOLS = DOUT / 4;
    constexpr int TROWS = 256 / TCOLS;
    constexpr int ROWS  = TROWS * 4;
    constexpr int HST   = DIN + 1;
    __shared__ float sh_h[ROWS * HST];

    const int tid = threadIdx.x;
    const int tc = tid % TCOLS;
    const int tr = tid / TCOLS;
    const int row0 = blockIdx.x * ROWS;

    for (int i = tid; i < ROWS * DIN; i += 256) {
        int r = i / DIN, k = i - r * DIN;
        float v = (row0 + r < nrows) ? H[(size_t)(row0 + r) * DIN + k] : 0.f;
        sh_h[r * HST + k] = v;
    }
    __syncthreads();

    float acc[4][4] = {};
    const float* wbase = W + tc * 4;
    const float* h0p = &sh_h[(tr * 4 + 0) * HST];
    const float* h1p = &sh_h[(tr * 4 + 1) * HST];
    const float* h2p = &sh_h[(tr * 4 + 2) * HST];
    const float* h3p = &sh_h[(tr * 4 + 3) * HST];

#pragma unroll 4
    for (int k = 0; k < DIN; k++) {
        float4 w = *reinterpret_cast<const float4*>(wbase + (size_t)k * DOUT);
        float a = h0p[k], b = h1p[k], c = h2p[k], d = h3p[k];
        acc[0][0] += a * w.x; acc[0][1] += a * w.y; acc[0][2] += a * w.z; acc[0][3] += a * w.w;
        acc[1][0] += b * w.x; acc[1][1] += b * w.y; acc[1][2] += b * w.z; acc[1][3] += b * w.w;
        acc[2][0] += c * w.x; acc[2][1] += c * w.y; acc[2][2] += c * w.z; acc[2][3] += c * w.w;
        acc[3][0] += d * w.x; acc[3][1] += d * w.y; acc[3][2] += d * w.z; acc[3][3] += d * w.w;
    }

    float4 bj = make_float4(0.f, 0.f, 0.f, 0.f);
    if (bias) bj = *reinterpret_cast<const float4*>(bias + tc * 4);

#pragma unroll
    for (int i = 0; i < 4; i++) {
        int row = row0 + tr * 4 + i;
        if (row < nrows) {
            float4 v = make_float4(acc[i][0] + bj.x, acc[i][1] + bj.y,
                                   acc[i][2] + bj.z, acc[i][3] + bj.w);
            *reinterpret_cast<float4*>(out + (size_t)row * DOUT + tc * 4) = v;
        }
    }
}

// ---------------- propagation: agg[tgt] += w * t[src], one warp per edge -----
template<int D>
__global__ __launch_bounds__(256) void prop_kernel(
    const float* __restrict__ t, const int* __restrict__ ei,
    const float* __restrict__ ew, float* __restrict__ agg, int E)
{
    int gw = (blockIdx.x * blockDim.x + threadIdx.x) >> 5;
    int lane = threadIdx.x & 31;
    if (gw >= E) return;

    long long src, tgt;
    if (g_is64) {
        const long long* p = (const long long*)ei;
        src = p[gw]; tgt = p[E + gw];
    } else {
        src = ei[gw]; tgt = ei[E + gw];
    }
    float w = ew[gw];
    const float* sp = t + (size_t)src * D;
    float* dp = agg + (size_t)tgt * D;

    if (D == 128) {
        float4 v = *reinterpret_cast<const float4*>(sp + lane * 4);
        red_add_v4(dp + lane * 4, v.x * w, v.y * w, v.z * w, v.w * w);
    } else {
        float2 v = *reinterpret_cast<const float2*>(sp + lane * 2);
        red_add_v2(dp + lane * 2, v.x * w, v.y * w);
    }
}

// ---------------- combine: h = tanh(cin*(ai+bi) + cout*(ao+bo) + resid) -----
template<int D>
__global__ void combine_kernel(
    const float* __restrict__ ai, const float* __restrict__ ao,
    const float* __restrict__ bmi, const float* __restrict__ bsi,
    const float* __restrict__ bmo, const float* __restrict__ bso,
    const float* __restrict__ cin, const float* __restrict__ cout,
    const float* __restrict__ resid, float* __restrict__ hout, int total)
{
    int idx = blockIdx.x * blockDim.x + threadIdx.x;
    if (idx >= total) return;
    int n = idx / D, j = idx % D;
    float ic = ai[idx] + bmi[j] + bsi[j];
    float oc = ao[idx] + bmo[j] + bso[j];
    hout[idx] = tanhf(cin[n] * ic + cout[n] * oc + resid[idx]);
}

// ---------------- decoder: logits -> log_softmax, plus L2-normalized emb ----
__global__ __launch_bounds__(128) void decoder_kernel(
    const float* __restrict__ h2, const float* __restrict__ W,
    const float* __restrict__ b, float* __restrict__ logp, float* __restrict__ emb)
{
    const int n = blockIdx.x;
    const int j = threadIdx.x;
    __shared__ float sh[D2];
    __shared__ float red[CLS];

    if (j < D2) sh[j] = h2[(size_t)n * D2 + j];
    __syncthreads();

    float acc = b[j];
#pragma unroll 8
    for (int k = 0; k < D2; k++) acc += sh[k] * W[(size_t)k * CLS + j];

    red[j] = acc; __syncthreads();
#pragma unroll
    for (int s = 64; s > 0; s >>= 1) {
        if (j < s) red[j] = fmaxf(red[j], red[j + s]);
        __syncthreads();
    }
    float mx = red[0]; __syncthreads();

    red[j] = expf(acc - mx); __syncthreads();
#pragma unroll
    for (int s = 64; s > 0; s >>= 1) {
        if (j < s) red[j] += red[j + s];
        __syncthreads();
    }
    float lse = mx + logf(red[0]); __syncthreads();
    logp[(size_t)n * CLS + j] = acc - lse;

    red[j] = (j < D2) ? sh[j] * sh[j] : 0.f; __syncthreads();
#pragma unroll
    for (int s = 64; s > 0; s >>= 1) {
        if (j < s) red[j] += red[j + s];
        __syncthreads();
    }
    if (j < D2) emb[(size_t)n * D2 + j] = sh[j] / (sqrtf(red[0]) + 1e-12f);
}

// ---------------- host ----------------
extern "C" void kernel_launch(void* const* d_in, const int* in_sizes, int n_in,
                              void* d_out, int out_size)
{
    const float* x      = (const float*)d_in[0];
    const int*   ei_in  = (const int*)d_in[1];   // dtype auto-detected (int32/int64)
    const float* ew_in  = (const float*)d_in[2];
    const int*   ei_out = (const int*)d_in[3];
    const float* ew_out = (const float*)d_in[4];
    const float* pe     = (const float*)d_in[5];

    const float* Wmi0 = (const float*)d_in[6];
    const float* Wmo0 = (const float*)d_in[7];
    const float* Ws0  = (const float*)d_in[8];
    const float* bmi0 = (const float*)d_in[9];
    const float* bmo0 = (const float*)d_in[10];
    const float* bsi0 = (const float*)d_in[11];
    const float* bso0 = (const float*)d_in[12];
    const float* cin0 = (const float*)d_in[13];
    const float* cout0= (const float*)d_in[14];

    const float* Wmi1 = (const float*)d_in[15];
    const float* Wmo1 = (const float*)d_in[16];
    const float* Ws1  = (const float*)d_in[17];
    const float* bmi1 = (const float*)d_in[18];
    const float* bmo1 = (const float*)d_in[19];
    const float* bsi1 = (const float*)d_in[20];
    const float* bso1 = (const float*)d_in[21];
    const float* cin1 = (const float*)d_in[22];
    const float* cout1= (const float*)d_in[23];

    const float* resW = (const float*)d_in[24];
    const float* resb = (const float*)d_in[25];
    const float* decW = (const float*)d_in[26];
    const float* decb = (const float*)d_in[27];

    float *h0, *t0, *t1, *a0, *a1, *h1, *res, *h2, *wc;
    cudaGetSymbolAddress((void**)&h0,  g_h0);
    cudaGetSymbolAddress((void**)&t0,  g_t0);
    cudaGetSymbolAddress((void**)&t1,  g_t1);
    cudaGetSymbolAddress((void**)&a0,  g_a0);
    cudaGetSymbolAddress((void**)&a1,  g_a1);
    cudaGetSymbolAddress((void**)&h1,  g_h1);
    cudaGetSymbolAddress((void**)&res, g_res);
    cudaGetSymbolAddress((void**)&h2,  g_h2);
    cudaGetSymbolAddress((void**)&wc,  g_wc);

    float* wc_in0  = wc;
    float* wc_out0 = wc + 128 * 128;
    float* wc_in1  = wc + 2 * 128 * 128;
    float* wc_out1 = wc + 2 * 128 * 128 + 128 * 64;

    const int N = NN, E = EE;
    const int TPB = 256;

    detect_kernel<<<1, 32>>>(ei_in);
    pe_kernel<<<(N * D0 + TPB - 1) / TPB, TPB>>>(x, pe, h0, N * D0);

    addw_kernel<<<(128 * 128 + TPB - 1) / TPB, TPB>>>(Wmi0, Ws0, wc_in0, 128 * 128);
    addw_kernel<<<(128 * 128 + TPB - 1) / TPB, TPB>>>(Wmo0, Ws0, wc_out0, 128 * 128);
    addw_kernel<<<(128 * 64 + TPB - 1) / TPB, TPB>>>(Wmi1, Ws1, wc_in1, 128 * 64);
    addw_kernel<<<(128 * 64 + TPB - 1) / TPB, TPB>>>(Wmo1, Ws1, wc_out1, 128 * 64);

    // ---- layer 0 ----
    zero_kernel<<<1024, TPB>>>(a0, N * D1);
    zero_kernel<<<1024, TPB>>>(a1, N * D1);

    {
        int blocks = (N + 31) / 32;
        gemm_kernel<128, 128><<<blocks, 256>>>(h0, wc_in0,  nullptr, t0, N);
        gemm_kernel<128, 128><<<blocks, 256>>>(h0, wc_out0, nullptr, t1, N);
    }
    {
        int blocks = (E * 32 + TPB - 1) / TPB;
        prop_kernel<128><<<blocks, TPB>>>(t0, ei_in,  ew_in,  a0, E);
        prop_kernel<128><<<blocks, TPB>>>(t1, ei_out, ew_out, a1, E);
    }
    combine_kernel<128><<<(N * D1 + TPB - 1) / TPB, TPB>>>(
        a0, a1, bmi0, bsi0, bmo0, bso0, cin0, cout0, h0, h1, N * D1);

    // ---- layer 1 ----
    zero_kernel<<<1024, TPB>>>(a0, N * D2);
    zero_kernel<<<1024, TPB>>>(a1, N * D2);

    {
        int blocks = (N + 63) / 64;
        gemm_kernel<128, 64><<<blocks, 256>>>(h1, wc_in1,  nullptr, t0, N);
        gemm_kernel<128, 64><<<blocks, 256>>>(h1, wc_out1, nullptr, t1, N);
        gemm_kernel<128, 64><<<blocks, 256>>>(h1, resW, resb, res, N);
    }
    {
        int blocks = (E * 32 + TPB - 1) / TPB;
        prop_kernel<64><<<blocks, TPB>>>(t0, ei_in,  ew_in,  a0, E);
        prop_kernel<64><<<blocks, TPB>>>(t1, ei_out, ew_out, a1, E);
    }
    combine_kernel<64><<<(N * D2 + TPB - 1) / TPB, TPB>>>(
        a0, a1, bmi1, bsi1, bmo1, bso1, cin1, cout1, res, h2, N * D2);

    // ---- decoder + log_softmax + emb ----
    float* out = (float*)d_out;
    decoder_kernel<<<N, 128>>>(h2, decW, decb, out, out + (size_t)N * CLS);
}

// round 2
// speedup vs baseline: 1.8798x; 1.8798x over previous
#include <cuda_runtime.h>
#include <math.h>

#define NN 50000
#define EE 800000
#define D0 128
#define D2 64
#define CLS 128

// ---------------- static device scratch ----------------
__device__ float g_h0[NN * 128];
__device__ float g_t [NN * 256];
__device__ float g_u [NN * 128];
__device__ float g_res[NN * 64];
__device__ float g_h1[NN * 128];
__device__ float g_h2[NN * 64];
__device__ float g_wc0[128 * 256];
__device__ float g_wc1[128 * 128];
__device__ float g_bsum[128 + 128 + 64 + 64];
__device__ int   g_deg_in[NN];
__device__ int   g_deg_out[NN];
__device__ int   g_rp_in[NN + 1];
__device__ int   g_rp_out[NN + 1];
__device__ int   g_cur_in[NN];
__device__ int   g_cur_out[NN];
__device__ int   g_csrc_in[EE];
__device__ float g_cw_in[EE];
__device__ int   g_csrc_out[EE];
__device__ float g_cw_out[EE];
__device__ int   g_is64;

// ---------------- misc small kernels ----------------
__global__ void detect_kernel(const int* __restrict__ ei) {
    if (threadIdx.x == 0 && blockIdx.x == 0) {
        int z = 0;
        for (int i = 1; i < 129; i += 2) z |= ei[i];
        g_is64 = (z == 0) ? 1 : 0;
    }
}

__global__ void zero_deg_kernel(int* __restrict__ a, int* __restrict__ b, int n) {
    int i = blockIdx.x * blockDim.x + threadIdx.x;
    if (i < n) { a[i] = 0; b[i] = 0; }
}

__global__ void pe_kernel(const float* __restrict__ x, const float* __restrict__ pe,
                          float* __restrict__ h0, int total) {
    int idx = blockIdx.x * blockDim.x + threadIdx.x;
    if (idx < total) h0[idx] = x[idx] + pe[idx & 127];
}

// build combined weights + combined biases
__global__ void prep_kernel(
    const float* __restrict__ Wmi0, const float* __restrict__ Wmo0, const float* __restrict__ Ws0,
    const float* __restrict__ Wmi1, const float* __restrict__ Wmo1, const float* __restrict__ Ws1,
    const float* __restrict__ bmi0, const float* __restrict__ bsi0,
    const float* __restrict__ bmo0, const float* __restrict__ bso0,
    const float* __restrict__ bmi1, const float* __restrict__ bsi1,
    const float* __restrict__ bmo1, const float* __restrict__ bso1,
    float* __restrict__ wc0, float* __restrict__ wc1, float* __restrict__ bsum)
{
    int i = blockIdx.x * blockDim.x + threadIdx.x;
    if (i < 128 * 256) {
        int k = i >> 8, j = i & 255;
        float w = (j < 128) ? Wmi0[k * 128 + j] : Wmo0[k * 128 + (j - 128)];
        wc0[i] = w + Ws0[k * 128 + (j & 127)];
        return;
    }
    int i2 = i - 128 * 256;
    if (i2 < 128 * 128) {
        int k = i2 >> 7, j = i2 & 127;
        float w = (j < 64) ? Wmi1[k * 64 + j] : Wmo1[k * 64 + (j - 64)];
        wc1[i2] = w + Ws1[k * 64 + (j & 63)];
        return;
    }
    int i3 = i2 - 128 * 128;
    if (i3 < 128)       bsum[i3]       = bmi0[i3] + bsi0[i3];
    else if (i3 < 256)  bsum[i3]       = bmo0[i3 - 128] + bso0[i3 - 128];
    else if (i3 < 320)  bsum[i3]       = bmi1[i3 - 256] + bsi1[i3 - 256];
    else if (i3 < 384)  bsum[i3]       = bmo1[i3 - 320] + bso1[i3 - 320];
}

// ---------------- CSR build ----------------
__global__ void count_kernel(const int* __restrict__ ei, int* __restrict__ deg, int E) {
    int e = blockIdx.x * blockDim.x + threadIdx.x;
    if (e >= E) return;
    int tgt;
    if (g_is64) tgt = (int)((const long long*)ei)[E + e];
    else        tgt = ei[E + e];
    atomicAdd(deg + tgt, 1);
}

__global__ __launch_bounds__(1024) void scan_kernel(
    const int* __restrict__ deg_in, const int* __restrict__ deg_out,
    int* __restrict__ rp_in, int* __restrict__ rp_out,
    int* __restrict__ cur_in, int* __restrict__ cur_out, int n)
{
    const int* deg = blockIdx.x ? deg_out : deg_in;
    int* rp  = blockIdx.x ? rp_out  : rp_in;
    int* cur = blockIdx.x ? cur_out : cur_in;
    __shared__ int wsum[32];
    int tid = threadIdx.x, lane = tid & 31, wid = tid >> 5;
    int carry = 0;
    for (int base = 0; base < n; base += 1024) {
        int i = base + tid;
        int x = (i < n) ? deg[i] : 0;
        int v = x;
#pragma unroll
        for (int off = 1; off < 32; off <<= 1) {
            int t = __shfl_up_sync(0xffffffffu, v, off);
            if (lane >= off) v += t;
        }
        if (lane == 31) wsum[wid] = v;
        __syncthreads();
        if (wid == 0) {
            int w = wsum[lane];
#pragma unroll
            for (int off = 1; off < 32; off <<= 1) {
                int t = __shfl_up_sync(0xffffffffu, w, off);
                if (lane >= off) w += t;
            }
            wsum[lane] = w;
        }
        __syncthreads();
        int woff = wid ? wsum[wid - 1] : 0;
        int total = wsum[31];
        if (i < n) {
            int excl = carry + woff + v - x;
            rp[i] = excl;
            cur[i] = excl;
        }
        carry += total;
        __syncthreads();
    }
    if (tid == 0) rp[n] = carry;
}

__global__ void scatter_kernel(const int* __restrict__ ei, const float* __restrict__ ew,
                               int* __restrict__ cur, int* __restrict__ csrc,
                               float* __restrict__ cw, int E)
{
    int e = blockIdx.x * blockDim.x + threadIdx.x;
    if (e >= E) return;
    int src, tgt;
    if (g_is64) {
        const long long* p = (const long long*)ei;
        src = (int)p[e]; tgt = (int)p[E + e];
    } else {
        src = ei[e]; tgt = ei[E + e];
    }
    int pos = atomicAdd(cur + tgt, 1);
    csrc[pos] = src;
    cw[pos]   = ew[e];
}

// ---------------- GEMM: out = H @ W (+bias), 8x4 / 4x4 register tiles ------
template<int DIN, int DOUT, int TR>
__global__ __launch_bounds__(256) void gemm_kernel(
    const float* __restrict__ H, const float* __restrict__ W,
    const float* __restrict__ bias, float* __restrict__ out, int nrows)
{
    constexpr int TCOLS = DOUT / 4;
    constexpr int TROWS = 256 / TCOLS;
    constexpr int ROWS  = TROWS * TR;
    constexpr int HST   = DIN + 1;
    __shared__ float sh[ROWS * HST];

    const int tid = threadIdx.x;
    const int tc = tid % TCOLS;
    const int tr = tid / TCOLS;
    const int row0 = blockIdx.x * ROWS;

    for (int i = tid; i < ROWS * DIN; i += 256) {
        int r = i / DIN, k = i - r * DIN;
        sh[r * HST + k] = (row0 + r < nrows) ? H[(size_t)(row0 + r) * DIN + k] : 0.f;
    }
    __syncthreads();

    float acc[TR][4] = {};
    const float* wp = W + tc * 4;
    const float* hp = &sh[tr * TR * HST];

#pragma unroll 2
    for (int k = 0; k < DIN; k++) {
        float4 w = *reinterpret_cast<const float4*>(wp + (size_t)k * DOUT);
#pragma unroll
        for (int i = 0; i < TR; i++) {
            float a = hp[i * HST + k];
            acc[i][0] += a * w.x; acc[i][1] += a * w.y;
            acc[i][2] += a * w.z; acc[i][3] += a * w.w;
        }
    }

    float4 bj = make_float4(0.f, 0.f, 0.f, 0.f);
    if (bias) bj = *reinterpret_cast<const float4*>(bias + tc * 4);

#pragma unroll
    for (int i = 0; i < TR; i++) {
        int row = row0 + tr * TR + i;
        if (row < nrows) {
            float4 v = make_float4(acc[i][0] + bj.x, acc[i][1] + bj.y,
                                   acc[i][2] + bj.z, acc[i][3] + bj.w);
            *reinterpret_cast<float4*>(out + (size_t)row * DOUT + tc * 4) = v;
        }
    }
}

// ---------------- layer-0 gather+combine: warp per node --------------------
__global__ __launch_bounds__(256) void gather0_kernel(
    const float* __restrict__ t,
    const int* __restrict__ rpi, const int* __restrict__ si, const float* __restrict__ wi,
    const int* __restrict__ rpo, const int* __restrict__ so, const float* __restrict__ wo,
    const float* __restrict__ bsum,
    const float* __restrict__ cin, const float* __restrict__ cout,
    const float* __restrict__ h0, float* __restrict__ h1, int n)
{
    int node = (blockIdx.x * 256 + threadIdx.x) >> 5;
    int lane = threadIdx.x & 31;
    if (node >= n) return;

    float4 ic = make_float4(0.f, 0.f, 0.f, 0.f);
    float4 oc = make_float4(0.f, 0.f, 0.f, 0.f);

    int s = rpi[node], e = rpi[node + 1];
#pragma unroll 4
    for (int k = s; k < e; k++) {
        int   src = __ldg(si + k);
        float w   = __ldg(wi + k);
        float4 v = *reinterpret_cast<const float4*>(t + (size_t)src * 256 + lane * 4);
        ic.x += w * v.x; ic.y += w * v.y; ic.z += w * v.z; ic.w += w * v.w;
    }
    s = rpo[node]; e = rpo[node + 1];
#pragma unroll 4
    for (int k = s; k < e; k++) {
        int   src = __ldg(so + k);
        float w   = __ldg(wo + k);
        float4 v = *reinterpret_cast<const float4*>(t + (size_t)src * 256 + 128 + lane * 4);
        oc.x += w * v.x; oc.y += w * v.y; oc.z += w * v.z; oc.w += w * v.w;
    }

    float ci = __ldg(cin + node), co = __ldg(cout + node);
    float4 bi = *reinterpret_cast<const float4*>(bsum + lane * 4);
    float4 bo = *reinterpret_cast<const float4*>(bsum + 128 + lane * 4);
    float4 r  = *reinterpret_cast<const float4*>(h0 + (size_t)node * 128 + lane * 4);
    float4 o;
    o.x = tanhf(ci * (ic.x + bi.x) + co * (oc.x + bo.x) + r.x);
    o.y = tanhf(ci * (ic.y + bi.y) + co * (oc.y + bo.y) + r.y);
    o.z = tanhf(ci * (ic.z + bi.z) + co * (oc.z + bo.z) + r.z);
    o.w = tanhf(ci * (ic.w + bi.w) + co * (oc.w + bo.w) + r.w);
    *reinterpret_cast<float4*>(h1 + (size_t)node * 128 + lane * 4) = o;
}

// ---------------- layer-1 gather+combine: warp per node --------------------
__global__ __launch_bounds__(256) void gather1_kernel(
    const float* __restrict__ u,
    const int* __restrict__ rpi, const int* __restrict__ si, const float* __restrict__ wi,
    const int* __restrict__ rpo, const int* __restrict__ so, const float* __restrict__ wo,
    const float* __restrict__ bsum,
    const float* __restrict__ cin, const float* __restrict__ cout,
    const float* __restrict__ res, float* __restrict__ h2, int n)
{
    int node = (blockIdx.x * 256 + threadIdx.x) >> 5;
    int lane = threadIdx.x & 31;
    if (node >= n) return;

    float2 ic = make_float2(0.f, 0.f);
    float2 oc = make_float2(0.f, 0.f);

    int s = rpi[node], e = rpi[node + 1];
#pragma unroll 4
    for (int k = s; k < e; k++) {
        int   src = __ldg(si + k);
        float w   = __ldg(wi + k);
        float2 v = *reinterpret_cast<const float2*>(u + (size_t)src * 128 + lane * 2);
        ic.x += w * v.x; ic.y += w * v.y;
    }
    s = rpo[node]; e = rpo[node + 1];
#pragma unroll 4
    for (int k = s; k < e; k++) {
        int   src = __ldg(so + k);
        float w   = __ldg(wo + k);
        float2 v = *reinterpret_cast<const float2*>(u + (size_t)src * 128 + 64 + lane * 2);
        oc.x += w * v.x; oc.y += w * v.y;
    }

    float ci = __ldg(cin + node), co = __ldg(cout + node);
    float2 bi = *reinterpret_cast<const float2*>(bsum + 256 + lane * 2);
    float2 bo = *reinterpret_cast<const float2*>(bsum + 320 + lane * 2);
    float2 r  = *reinterpret_cast<const float2*>(res + (size_t)node * 64 + lane * 2);
    float2 o;
    o.x = tanhf(ci * (ic.x + bi.x) + co * (oc.x + bo.x) + r.x);
    o.y = tanhf(ci * (ic.y + bi.y) + co * (oc.y + bo.y) + r.y);
    *reinterpret_cast<float2*>(h2 + (size_t)node * 64 + lane * 2) = o;
}

// ---------------- decoder: warp handles 2 nodes -----------------------------
__device__ __forceinline__ void logsm_store(float4 acc, int node, int lane,
                                            float* __restrict__ logp, int n) {
    float m = fmaxf(fmaxf(acc.x, acc.y), fmaxf(acc.z, acc.w));
#pragma unroll
    for (int off = 16; off > 0; off >>= 1)
        m = fmaxf(m, __shfl_xor_sync(0xffffffffu, m, off));
    float s = expf(acc.x - m) + expf(acc.y - m) + expf(acc.z - m) + expf(acc.w - m);
#pragma unroll
    for (int off = 16; off > 0; off >>= 1)
        s += __shfl_xor_sync(0xffffffffu, s, off);
    float lse = m + logf(s);
    if (node < n) {
        float4 o = make_float4(acc.x - lse, acc.y - lse, acc.z - lse, acc.w - lse);
        *reinterpret_cast<float4*>(logp + (size_t)node * CLS + lane * 4) = o;
    }
}

__device__ __forceinline__ void emb_store(const float* __restrict__ h, int node, int lane,
                                          float* __restrict__ emb, int n) {
    float2 v = *reinterpret_cast<const float2*>(h + lane * 2);
    float sq = v.x * v.x + v.y * v.y;
#pragma unroll
    for (int off = 16; off > 0; off >>= 1)
        sq += __shfl_xor_sync(0xffffffffu, sq, off);
    float inv = 1.f / (sqrtf(sq) + 1e-12f);
    if (node < n) {
        float2 o = make_float2(v.x * inv, v.y * inv);
        *reinterpret_cast<float2*>(emb + (size_t)node * 64 + lane * 2) = o;
    }
}

__global__ __launch_bounds__(256) void decoder_kernel(
    const float* __restrict__ h2, const float* __restrict__ W,
    const float* __restrict__ b, float* __restrict__ logp,
    float* __restrict__ emb, int n)
{
    __shared__ float sh[16 * 64];
    int tid = threadIdx.x;
    int node0 = blockIdx.x * 16;

    for (int i = tid; i < 16 * 64; i += 256) {
        int nd = node0 + (i >> 6);
        sh[i] = (nd < n) ? h2[(size_t)nd * 64 + (i & 63)] : 0.f;
    }
    __syncthreads();

    int wid = tid >> 5, lane = tid & 31;
    int la = wid * 2, lb = la + 1;
    const float* ha = sh + la * 64;
    const float* hb = sh + lb * 64;

    float4 bj = *reinterpret_cast<const float4*>(b + lane * 4);
    float4 acc0 = bj, acc1 = bj;

#pragma unroll 4
    for (int k = 0; k < 64; k++) {
        float4 w = *reinterpret_cast<const float4*>(W + (size_t)k * CLS + lane * 4);
        float a = ha[k], c = hb[k];
        acc0.x += a * w.x; acc0.y += a * w.y; acc0.z += a * w.z; acc0.w += a * w.w;
        acc1.x += c * w.x; acc1.y += c * w.y; acc1.z += c * w.z; acc1.w += c * w.w;
    }

    logsm_store(acc0, node0 + la, lane, logp, n);
    logsm_store(acc1, node0 + lb, lane, logp, n);
    emb_store(ha, node0 + la, lane, emb, n);
    emb_store(hb, node0 + lb, lane, emb, n);
}

// ---------------- host ----------------
extern "C" void kernel_launch(void* const* d_in, const int* in_sizes, int n_in,
                              void* d_out, int out_size)
{
    const float* x      = (const float*)d_in[0];
    const int*   ei_in  = (const int*)d_in[1];
    const float* ew_in  = (const float*)d_in[2];
    const int*   ei_out = (const int*)d_in[3];
    const float* ew_out = (const float*)d_in[4];
    const float* pe     = (const float*)d_in[5];

    const float* Wmi0 = (const float*)d_in[6];
    const float* Wmo0 = (const float*)d_in[7];
    const float* Ws0  = (const float*)d_in[8];
    const float* bmi0 = (const float*)d_in[9];
    const float* bmo0 = (const float*)d_in[10];
    const float* bsi0 = (const float*)d_in[11];
    const float* bso0 = (const float*)d_in[12];
    const float* cin0 = (const float*)d_in[13];
    const float* cout0= (const float*)d_in[14];

    const float* Wmi1 = (const float*)d_in[15];
    const float* Wmo1 = (const float*)d_in[16];
    const float* Ws1  = (const float*)d_in[17];
    const float* bmi1 = (const float*)d_in[18];
    const float* bmo1 = (const float*)d_in[19];
    const float* bsi1 = (const float*)d_in[20];
    const float* bso1 = (const float*)d_in[21];
    const float* cin1 = (const float*)d_in[22];
    const float* cout1= (const float*)d_in[23];

    const float* resW = (const float*)d_in[24];
    const float* resb = (const float*)d_in[25];
    const float* decW = (const float*)d_in[26];
    const float* decb = (const float*)d_in[27];

    float *h0, *t, *u, *res, *h1, *h2, *wc0, *wc1, *bsum;
    float *cw_in, *cw_out;
    int *deg_in, *deg_out, *rp_in, *rp_out, *cur_in, *cur_out, *csrc_in, *csrc_out;
    cudaGetSymbolAddress((void**)&h0,  g_h0);
    cudaGetSymbolAddress((void**)&t,   g_t);
    cudaGetSymbolAddress((void**)&u,   g_u);
    cudaGetSymbolAddress((void**)&res, g_res);
    cudaGetSymbolAddress((void**)&h1,  g_h1);
    cudaGetSymbolAddress((void**)&h2,  g_h2);
    cudaGetSymbolAddress((void**)&wc0, g_wc0);
    cudaGetSymbolAddress((void**)&wc1, g_wc1);
    cudaGetSymbolAddress((void**)&bsum,g_bsum);
    cudaGetSymbolAddress((void**)&deg_in,  g_deg_in);
    cudaGetSymbolAddress((void**)&deg_out, g_deg_out);
    cudaGetSymbolAddress((void**)&rp_in,   g_rp_in);
    cudaGetSymbolAddress((void**)&rp_out,  g_rp_out);
    cudaGetSymbolAddress((void**)&cur_in,  g_cur_in);
    cudaGetSymbolAddress((void**)&cur_out, g_cur_out);
    cudaGetSymbolAddress((void**)&csrc_in, g_csrc_in);
    cudaGetSymbolAddress((void**)&csrc_out,g_csrc_out);
    cudaGetSymbolAddress((void**)&cw_in,   g_cw_in);
    cudaGetSymbolAddress((void**)&cw_out,  g_cw_out);

    const int N = NN, E = EE, TPB = 256;

    detect_kernel<<<1, 32>>>(ei_in);
    zero_deg_kernel<<<(N + TPB - 1) / TPB, TPB>>>(deg_in, deg_out, N);
    pe_kernel<<<(N * D0 + TPB - 1) / TPB, TPB>>>(x, pe, h0, N * D0);
    prep_kernel<<<(128 * 256 + 128 * 128 + 384 + TPB - 1) / TPB, TPB>>>(
        Wmi0, Wmo0, Ws0, Wmi1, Wmo1, Ws1,
        bmi0, bsi0, bmo0, bso0, bmi1, bsi1, bmo1, bso1,
        wc0, wc1, bsum);

    // CSR build for both edge sets
    count_kernel<<<(E + TPB - 1) / TPB, TPB>>>(ei_in,  deg_in,  E);
    count_kernel<<<(E + TPB - 1) / TPB, TPB>>>(ei_out, deg_out, E);
    scan_kernel<<<2, 1024>>>(deg_in, deg_out, rp_in, rp_out, cur_in, cur_out, N);
    scatter_kernel<<<(E + TPB - 1) / TPB, TPB>>>(ei_in,  ew_in,  cur_in,  csrc_in,  cw_in,  E);
    scatter_kernel<<<(E + TPB - 1) / TPB, TPB>>>(ei_out, ew_out, cur_out, csrc_out, cw_out, E);

    // ---- layer 0: fused dual GEMM (128 -> 256) then gather+combine ----
    gemm_kernel<128, 256, 8><<<(N + 31) / 32, 256>>>(h0, wc0, nullptr, t, N);
    gather0_kernel<<<(N * 32 + TPB - 1) / TPB, TPB>>>(
        t, rp_in, csrc_in, cw_in, rp_out, csrc_out, cw_out,
        bsum, cin0, cout0, h0, h1, N);

    // ---- layer 1: fused dual GEMM (128 -> 128) + residual GEMM ----
    gemm_kernel<128, 128, 8><<<(N + 63) / 64, 256>>>(h1, wc1, nullptr, u, N);
    gemm_kernel<128, 64, 4><<<(N + 63) / 64, 256>>>(h1, resW, resb, res, N);
    gather1_kernel<<<(N * 32 + TPB - 1) / TPB, TPB>>>(
        u, rp_in, csrc_in, cw_in, rp_out, csrc_out, cw_out,
        bsum, cin1, cout1, res, h2, N);

    // ---- decoder + log_softmax + emb ----
    float* out = (float*)d_out;
    decoder_kernel<<<(N + 15) / 16, 256>>>(h2, decW, decb, out, out + (size_t)N * CLS, N);
}

// round 3
// speedup vs baseline: 2.2643x; 1.2046x over previous
#include <cuda_runtime.h>
#include <math.h>

#define NN 50000
#define EE 800000
#define CLS 128

// ---------------- static device scratch ----------------
__device__ float g_h0[NN * 128];
__device__ float g_t [NN * 256];
__device__ float g_u [NN * 192];
__device__ float g_h1[NN * 128];
__device__ float g_h2[NN * 64];
__device__ float4 g_blob0[16384];   // layer0 weights K=128,N=256, frag order, hi/lo
__device__ float4 g_blob1[12288];   // layer1 weights K=128,N=192 (incl res), frag order
__device__ float g_bsum[448];
__device__ int   g_deg_in[NN];
__device__ int   g_deg_out[NN];
__device__ int   g_rp_in[NN + 1];
__device__ int   g_rp_out[NN + 1];
__device__ int   g_cur_in[NN];
__device__ int   g_cur_out[NN];
__device__ int   g_csrc_in[EE];
__device__ float g_cw_in[EE];
__device__ int   g_csrc_out[EE];
__device__ float g_cw_out[EE];
__device__ int   g_is64;

// ---------------- tf32 helpers ----------------
__device__ __forceinline__ void split_tf32(float a, unsigned& hi, unsigned& lo) {
    asm("cvt.rna.tf32.f32 %0, %1;" : "=r"(hi) : "f"(a));
    float r = a - __uint_as_float(hi);
    asm("cvt.rna.tf32.f32 %0, %1;" : "=r"(lo) : "f"(r));
}

__device__ __forceinline__ void mma_tf32(float4& d,
    unsigned a0, unsigned a1, unsigned a2, unsigned a3,
    unsigned b0, unsigned b1)
{
    asm volatile(
        "mma.sync.aligned.m16n8k8.row.col.f32.tf32.tf32.f32 "
        "{%0,%1,%2,%3},{%4,%5,%6,%7},{%8,%9},{%0,%1,%2,%3};"
        : "+f"(d.x), "+f"(d.y), "+f"(d.z), "+f"(d.w)
        : "r"(a0), "r"(a1), "r"(a2), "r"(a3), "r"(b0), "r"(b1));
}

__device__ __forceinline__ void cp16(void* smem_dst, const void* gsrc, int sz) {
    unsigned du = (unsigned)__cvta_generic_to_shared(smem_dst);
    asm volatile("cp.async.cg.shared.global [%0], [%1], 16, %2;"
                 :: "r"(du), "l"(gsrc), "r"(sz));
}

// ---------------- misc small kernels ----------------
__global__ void detect_kernel(const int* __restrict__ ei) {
    if (threadIdx.x == 0 && blockIdx.x == 0) {
        int z = 0;
        for (int i = 1; i < 129; i += 2) z |= ei[i];
        g_is64 = (z == 0) ? 1 : 0;
    }
}

__global__ void zero_deg_kernel(int* __restrict__ a, int* __restrict__ b, int n) {
    int i = blockIdx.x * blockDim.x + threadIdx.x;
    if (i < n) { a[i] = 0; b[i] = 0; }
}

__global__ void pe_kernel(const float* __restrict__ x, const float* __restrict__ pe,
                          float* __restrict__ h0, int total) {
    int idx = blockIdx.x * blockDim.x + threadIdx.x;
    if (idx < total) h0[idx] = x[idx] + pe[idx & 127];
}

// build frag-ordered, hi/lo-split weight blobs + combined biases
__global__ void prep_kernel(
    const float* __restrict__ Wmi0, const float* __restrict__ Wmo0, const float* __restrict__ Ws0,
    const float* __restrict__ Wmi1, const float* __restrict__ Wmo1, const float* __restrict__ Ws1,
    const float* __restrict__ resW,
    const float* __restrict__ bmi0, const float* __restrict__ bsi0,
    const float* __restrict__ bmo0, const float* __restrict__ bso0,
    const float* __restrict__ bmi1, const float* __restrict__ bsi1,
    const float* __restrict__ bmo1, const float* __restrict__ bso1,
    const float* __restrict__ resb,
    float4* __restrict__ blob0, float4* __restrict__ blob1, float* __restrict__ bsum)
{
    int i = blockIdx.x * blockDim.x + threadIdx.x;
    if (i < 16384) {
        // layer0: K=128, N=256
        int lane = i & 31; int j = i >> 5;
        int nt = j & 7; j >>= 3;
        int ks = j & 15; j >>= 4;
        int nc = j;
        int n = nc * 64 + nt * 8 + (lane >> 2);
        int ka = ks * 8 + (lane & 3), kb = ka + 4;
        int nn = n & 127;
        float a = Ws0[ka * 128 + nn] + ((n < 128) ? Wmi0[ka * 128 + n] : Wmo0[ka * 128 + n - 128]);
        float b = Ws0[kb * 128 + nn] + ((n < 128) ? Wmi0[kb * 128 + n] : Wmo0[kb * 128 + n - 128]);
        unsigned ha, la, hb, lb;
        split_tf32(a, ha, la); split_tf32(b, hb, lb);
        blob0[i] = make_float4(__uint_as_float(ha), __uint_as_float(hb),
                               __uint_as_float(la), __uint_as_float(lb));
        return;
    }
    int i1 = i - 16384;
    if (i1 < 12288) {
        // layer1: K=128, N=192 (cols 0-63 in, 64-127 out, 128-191 res)
        int lane = i1 & 31; int j = i1 >> 5;
        int nt = j & 7; j >>= 3;
        int ks = j & 15; j >>= 4;
        int nc = j;
        int n = nc * 64 + nt * 8 + (lane >> 2);
        int ka = ks * 8 + (lane & 3), kb = ka + 4;
        float a, b;
        if (n < 128) {
            int nn = n & 63;
            a = Ws1[ka * 64 + nn] + ((n < 64) ? Wmi1[ka * 64 + n] : Wmo1[ka * 64 + n - 64]);
            b = Ws1[kb * 64 + nn] + ((n < 64) ? Wmi1[kb * 64 + n] : Wmo1[kb * 64 + n - 64]);
        } else {
            a = resW[ka * 64 + n - 128];
            b = resW[kb * 64 + n - 128];
        }
        unsigned ha, la, hb, lb;
        split_tf32(a, ha, la); split_tf32(b, hb, lb);
        blob1[i1] = make_float4(__uint_as_float(ha), __uint_as_float(hb),
                                __uint_as_float(la), __uint_as_float(lb));
        return;
    }
    int i2 = i1 - 12288;
    if (i2 < 128)       bsum[i2] = bmi0[i2] + bsi0[i2];
    else if (i2 < 256)  bsum[i2] = bmo0[i2 - 128] + bso0[i2 - 128];
    else if (i2 < 320)  bsum[i2] = bmi1[i2 - 256] + bsi1[i2 - 256];
    else if (i2 < 384)  bsum[i2] = bmo1[i2 - 320] + bso1[i2 - 320];
    else if (i2 < 448)  bsum[i2] = resb[i2 - 384];
}

// ---------------- CSR build ----------------
__global__ void count_kernel(const int* __restrict__ ei, int* __restrict__ deg, int E) {
    int e = blockIdx.x * blockDim.x + threadIdx.x;
    if (e >= E) return;
    int tgt;
    if (g_is64) tgt = (int)((const long long*)ei)[E + e];
    else        tgt = ei[E + e];
    atomicAdd(deg + tgt, 1);
}

__global__ __launch_bounds__(1024) void scan_kernel(
    const int* __restrict__ deg_in, const int* __restrict__ deg_out,
    int* __restrict__ rp_in, int* __restrict__ rp_out,
    int* __restrict__ cur_in, int* __restrict__ cur_out, int n)
{
    const int* deg = blockIdx.x ? deg_out : deg_in;
    int* rp  = blockIdx.x ? rp_out  : rp_in;
    int* cur = blockIdx.x ? cur_out : cur_in;
    __shared__ int wsum[32];
    int tid = threadIdx.x, lane = tid & 31, wid = tid >> 5;
    int carry = 0;
    for (int base = 0; base < n; base += 1024) {
        int i = base + tid;
        int x = (i < n) ? deg[i] : 0;
        int v = x;
#pragma unroll
        for (int off = 1; off < 32; off <<= 1) {
            int t = __shfl_up_sync(0xffffffffu, v, off);
            if (lane >= off) v += t;
        }
        if (lane == 31) wsum[wid] = v;
        __syncthreads();
        if (wid == 0) {
            int w = wsum[lane];
#pragma unroll
            for (int off = 1; off < 32; off <<= 1) {
                int t = __shfl_up_sync(0xffffffffu, w, off);
                if (lane >= off) w += t;
            }
            wsum[lane] = w;
        }
        __syncthreads();
        int woff = wid ? wsum[wid - 1] : 0;
        int total = wsum[31];
        if (i < n) {
            int excl = carry + woff + v - x;
            rp[i] = excl;
            cur[i] = excl;
        }
        carry += total;
        __syncthreads();
    }
    if (tid == 0) rp[n] = carry;
}

__global__ void scatter_kernel(const int* __restrict__ ei, const float* __restrict__ ew,
                               int* __restrict__ cur, int* __restrict__ csrc,
                               float* __restrict__ cw, int E)
{
    int e = blockIdx.x * blockDim.x + threadIdx.x;
    if (e >= E) return;
    int src, tgt;
    if (g_is64) {
        const long long* p = (const long long*)ei;
        src = (int)p[e]; tgt = (int)p[E + e];
    } else {
        src = ei[e]; tgt = ei[E + e];
    }
    int pos = atomicAdd(cur + tgt, 1);
    csrc[pos] = src;
    cw[pos]   = ew[e];
}

// ---------------- tensor-core GEMM: out[M x N] = H[M x 128] @ W ----------------
// CTA: 128 rows, 8 warps (warp = 16 rows x 64 cols per chunk). N chunked by 64.
// W blob is pre-split (hi/lo) and pre-shuffled to fragment order.
template<int N>
__global__ __launch_bounds__(256) void tgemm_kernel(
    const float* __restrict__ H, const float4* __restrict__ Wblob,
    float* __restrict__ out, int nrows)
{
    constexpr int K = 128;
    constexpr int CHUNKS = N / 64;
    constexpr int AST = K + 4;          // padded row stride (floats)
    extern __shared__ float smem[];
    float* shA  = smem;                 // 128 * AST
    float* shB0 = smem + 128 * AST;     // 16384 floats
    float* shB1 = shB0 + 16384;

    const int tid  = threadIdx.x;
    const int lane = tid & 31;
    const int wm   = (tid >> 5) * 16;   // warp's row base within tile
    const int g    = lane >> 2;
    const int row0 = blockIdx.x * 128;

    // stage A (zero-fill OOB rows)
#pragma unroll
    for (int i = 0; i < 16; i++) {
        int lin = tid + 256 * i;        // 4096 float4s
        int r = lin >> 5, c4 = (lin & 31) << 2;
        int sz = (row0 + r < nrows) ? 16 : 0;
        cp16(shA + r * AST + c4, H + (size_t)(row0 + r) * K + c4, sz);
    }
    // stage B chunk 0
#pragma unroll
    for (int i = 0; i < 16; i++) {
        int lin = tid + 256 * i;
        cp16(shB0 + lin * 4, Wblob + lin, 16);
    }
    asm volatile("cp.async.commit_group;");
    asm volatile("cp.async.wait_group 0;");
    __syncthreads();

    for (int c = 0; c < CHUNKS; c++) {
        // prefetch next B chunk into other buffer
        if (c + 1 < CHUNKS) {
            float* nb = ((c + 1) & 1) ? shB1 : shB0;
            const float4* src = Wblob + (size_t)(c + 1) * 4096;
#pragma unroll
            for (int i = 0; i < 16; i++) {
                int lin = tid + 256 * i;
                cp16(nb + lin * 4, src + lin, 16);
            }
            asm volatile("cp.async.commit_group;");
        }

        const float* shB = (c & 1) ? shB1 : shB0;
        float4 acc[8];
#pragma unroll
        for (int nt = 0; nt < 8; nt++) acc[nt] = make_float4(0.f, 0.f, 0.f, 0.f);

#pragma unroll 2
        for (int ks = 0; ks < 16; ks++) {
            int ka = ks * 8 + (lane & 3);
            const float* ap = shA + (wm + g) * AST + ka;
            float a0 = ap[0], a2 = ap[4];
            float a1 = ap[8 * AST], a3 = ap[8 * AST + 4];
            unsigned h0, l0, h1, l1, h2, l2, h3, l3;
            split_tf32(a0, h0, l0); split_tf32(a1, h1, l1);
            split_tf32(a2, h2, l2); split_tf32(a3, h3, l3);
            const uint4* bp = reinterpret_cast<const uint4*>(shB) + ks * 256 + lane;
#pragma unroll
            for (int nt = 0; nt < 8; nt++) {
                uint4 b = bp[nt * 32];
                mma_tf32(acc[nt], h0, h1, h2, h3, b.x, b.y);
                mma_tf32(acc[nt], h0, h1, h2, h3, b.z, b.w);
                mma_tf32(acc[nt], l0, l1, l2, l3, b.x, b.y);
            }
        }

        // store
        int r1 = row0 + wm + g, r2 = r1 + 8;
        int colb = c * 64 + 2 * (lane & 3);
#pragma unroll
        for (int nt = 0; nt < 8; nt++) {
            int col = colb + nt * 8;
            if (r1 < nrows)
                *reinterpret_cast<float2*>(out + (size_t)r1 * N + col) = make_float2(acc[nt].x, acc[nt].y);
            if (r2 < nrows)
                *reinterpret_cast<float2*>(out + (size_t)r2 * N + col) = make_float2(acc[nt].z, acc[nt].w);
        }

        asm volatile("cp.async.wait_group 0;");
        __syncthreads();
    }
}

// ---------------- layer-0 gather+combine: warp per node --------------------
__global__ __launch_bounds__(256) void gather0_kernel(
    const float* __restrict__ t,
    const int* __restrict__ rpi, const int* __restrict__ si, const float* __restrict__ wi,
    const int* __restrict__ rpo, const int* __restrict__ so, const float* __restrict__ wo,
    const float* __restrict__ bsum,
    const float* __restrict__ cin, const float* __restrict__ cout,
    const float* __restrict__ h0, float* __restrict__ h1, int n)
{
    int node = (blockIdx.x * 256 + threadIdx.x) >> 5;
    int lane = threadIdx.x & 31;
    if (node >= n) return;

    float4 ic = make_float4(0.f, 0.f, 0.f, 0.f);
    float4 oc = make_float4(0.f, 0.f, 0.f, 0.f);

    int s = rpi[node], e = rpi[node + 1];
#pragma unroll 4
    for (int k = s; k < e; k++) {
        int   src = __ldg(si + k);
        float w   = __ldg(wi + k);
        float4 v = *reinterpret_cast<const float4*>(t + (size_t)src * 256 + lane * 4);
        ic.x += w * v.x; ic.y += w * v.y; ic.z += w * v.z; ic.w += w * v.w;
    }
    s = rpo[node]; e = rpo[node + 1];
#pragma unroll 4
    for (int k = s; k < e; k++) {
        int   src = __ldg(so + k);
        float w   = __ldg(wo + k);
        float4 v = *reinterpret_cast<const float4*>(t + (size_t)src * 256 + 128 + lane * 4);
        oc.x += w * v.x; oc.y += w * v.y; oc.z += w * v.z; oc.w += w * v.w;
    }

    float ci = __ldg(cin + node), co = __ldg(cout + node);
    float4 bi = *reinterpret_cast<const float4*>(bsum + lane * 4);
    float4 bo = *reinterpret_cast<const float4*>(bsum + 128 + lane * 4);
    float4 r  = *reinterpret_cast<const float4*>(h0 + (size_t)node * 128 + lane * 4);
    float4 o;
    o.x = tanhf(ci * (ic.x + bi.x) + co * (oc.x + bo.x) + r.x);
    o.y = tanhf(ci * (ic.y + bi.y) + co * (oc.y + bo.y) + r.y);
    o.z = tanhf(ci * (ic.z + bi.z) + co * (oc.z + bo.z) + r.z);
    o.w = tanhf(ci * (ic.w + bi.w) + co * (oc.w + bo.w) + r.w);
    *reinterpret_cast<float4*>(h1 + (size_t)node * 128 + lane * 4) = o;
}

// ---------------- layer-1 gather+combine (u stride 192, res in cols 128+) --
__global__ __launch_bounds__(256) void gather1_kernel(
    const float* __restrict__ u,
    const int* __restrict__ rpi, const int* __restrict__ si, const float* __restrict__ wi,
    const int* __restrict__ rpo, const int* __restrict__ so, const float* __restrict__ wo,
    const float* __restrict__ bsum,
    const float* __restrict__ cin, const float* __restrict__ cout,
    float* __restrict__ h2, int n)
{
    int node = (blockIdx.x * 256 + threadIdx.x) >> 5;
    int lane = threadIdx.x & 31;
    if (node >= n) return;

    float2 ic = make_float2(0.f, 0.f);
    float2 oc = make_float2(0.f, 0.f);

    int s = rpi[node], e = rpi[node + 1];
#pragma unroll 4
    for (int k = s; k < e; k++) {
        int   src = __ldg(si + k);
        float w   = __ldg(wi + k);
        float2 v = *reinterpret_cast<const float2*>(u + (size_t)src * 192 + lane * 2);
        ic.x += w * v.x; ic.y += w * v.y;
    }
    s = rpo[node]; e = rpo[node + 1];
#pragma unroll 4
    for (int k = s; k < e; k++) {
        int   src = __ldg(so + k);
        float w   = __ldg(wo + k);
        float2 v = *reinterpret_cast<const float2*>(u + (size_t)src * 192 + 64 + lane * 2);
        oc.x += w * v.x; oc.y += w * v.y;
    }

    float ci = __ldg(cin + node), co = __ldg(cout + node);
    float2 bi = *reinterpret_cast<const float2*>(bsum + 256 + lane * 2);
    float2 bo = *reinterpret_cast<const float2*>(bsum + 320 + lane * 2);
    float2 rb = *reinterpret_cast<const float2*>(bsum + 384 + lane * 2);
    float2 r  = *reinterpret_cast<const float2*>(u + (size_t)node * 192 + 128 + lane * 2);
    float2 o;
    o.x = tanhf(ci * (ic.x + bi.x) + co * (oc.x + bo.x) + r.x + rb.x);
    o.y = tanhf(ci * (ic.y + bi.y) + co * (oc.y + bo.y) + r.y + rb.y);
    *reinterpret_cast<float2*>(h2 + (size_t)node * 64 + lane * 2) = o;
}

// ---------------- decoder: warp handles 2 nodes -----------------------------
__device__ __forceinline__ void logsm_store(float4 acc, int node, int lane,
                                            float* __restrict__ logp, int n) {
    float m = fmaxf(fmaxf(acc.x, acc.y), fmaxf(acc.z, acc.w));
#pragma unroll
    for (int off = 16; off > 0; off >>= 1)
        m = fmaxf(m, __shfl_xor_sync(0xffffffffu, m, off));
    float s = expf(acc.x - m) + expf(acc.y - m) + expf(acc.z - m) + expf(acc.w - m);
#pragma unroll
    for (int off = 16; off > 0; off >>= 1)
        s += __shfl_xor_sync(0xffffffffu, s, off);
    float lse = m + logf(s);
    if (node < n) {
        float4 o = make_float4(acc.x - lse, acc.y - lse, acc.z - lse, acc.w - lse);
        *reinterpret_cast<float4*>(logp + (size_t)node * CLS + lane * 4) = o;
    }
}

__device__ __forceinline__ void emb_store(const float* __restrict__ h, int node, int lane,
                                          float* __restrict__ emb, int n) {
    float2 v = *reinterpret_cast<const float2*>(h + lane * 2);
    float sq = v.x * v.x + v.y * v.y;
#pragma unroll
    for (int off = 16; off > 0; off >>= 1)
        sq += __shfl_xor_sync(0xffffffffu, sq, off);
    float inv = 1.f / (sqrtf(sq) + 1e-12f);
    if (node < n) {
        float2 o = make_float2(v.x * inv, v.y * inv);
        *reinterpret_cast<float2*>(emb + (size_t)node * 64 + lane * 2) = o;
    }
}

__global__ __launch_bounds__(256) void decoder_kernel(
    const float* __restrict__ h2, const float* __restrict__ W,
    const float* __restrict__ b, float* __restrict__ logp,
    float* __restrict__ emb, int n)
{
    __shared__ float sh[16 * 64];
    int tid = threadIdx.x;
    int node0 = blockIdx.x * 16;

    for (int i = tid; i < 16 * 64; i += 256) {
        int nd = node0 + (i >> 6);
        sh[i] = (nd < n) ? h2[(size_t)nd * 64 + (i & 63)] : 0.f;
    }
    __syncthreads();

    int wid = tid >> 5, lane = tid & 31;
    int la = wid * 2, lb = la + 1;
    const float* ha = sh + la * 64;
    const float* hb = sh + lb * 64;

    float4 bj = *reinterpret_cast<const float4*>(b + lane * 4);
    float4 acc0 = bj, acc1 = bj;

#pragma unroll 4
    for (int k = 0; k < 64; k++) {
        float4 w = *reinterpret_cast<const float4*>(W + (size_t)k * CLS + lane * 4);
        float a = ha[k], c = hb[k];
        acc0.x += a * w.x; acc0.y += a * w.y; acc0.z += a * w.z; acc0.w += a * w.w;
        acc1.x += c * w.x; acc1.y += c * w.y; acc1.z += c * w.z; acc1.w += c * w.w;
    }

    logsm_store(acc0, node0 + la, lane, logp, n);
    logsm_store(acc1, node0 + lb, lane, logp, n);
    emb_store(ha, node0 + la, lane, emb, n);
    emb_store(hb, node0 + lb, lane, emb, n);
}

// ---------------- host ----------------
extern "C" void kernel_launch(void* const* d_in, const int* in_sizes, int n_in,
                              void* d_out, int out_size)
{
    const float* x      = (const float*)d_in[0];
    const int*   ei_in  = (const int*)d_in[1];
    const float* ew_in  = (const float*)d_in[2];
    const int*   ei_out = (const int*)d_in[3];
    const float* ew_out = (const float*)d_in[4];
    const float* pe     = (const float*)d_in[5];

    const float* Wmi0 = (const float*)d_in[6];
    const float* Wmo0 = (const float*)d_in[7];
    const float* Ws0  = (const float*)d_in[8];
    const float* bmi0 = (const float*)d_in[9];
    const float* bmo0 = (const float*)d_in[10];
    const float* bsi0 = (const float*)d_in[11];
    const float* bso0 = (const float*)d_in[12];
    const float* cin0 = (const float*)d_in[13];
    const float* cout0= (const float*)d_in[14];

    const float* Wmi1 = (const float*)d_in[15];
    const float* Wmo1 = (const float*)d_in[16];
    const float* Ws1  = (const float*)d_in[17];
    const float* bmi1 = (const float*)d_in[18];
    const float* bmo1 = (const float*)d_in[19];
    const float* bsi1 = (const float*)d_in[20];
    const float* bso1 = (const float*)d_in[21];
    const float* cin1 = (const float*)d_in[22];
    const float* cout1= (const float*)d_in[23];

    const float* resW = (const float*)d_in[24];
    const float* resb = (const float*)d_in[25];
    const float* decW = (const float*)d_in[26];
    const float* decb = (const float*)d_in[27];

    float *h0, *t, *u, *h1, *h2, *bsum;
    float4 *blob0, *blob1;
    float *cw_in, *cw_out;
    int *deg_in, *deg_out, *rp_in, *rp_out, *cur_in, *cur_out, *csrc_in, *csrc_out;
    cudaGetSymbolAddress((void**)&h0,  g_h0);
    cudaGetSymbolAddress((void**)&t,   g_t);
    cudaGetSymbolAddress((void**)&u,   g_u);
    cudaGetSymbolAddress((void**)&h1,  g_h1);
    cudaGetSymbolAddress((void**)&h2,  g_h2);
    cudaGetSymbolAddress((void**)&blob0, g_blob0);
    cudaGetSymbolAddress((void**)&blob1, g_blob1);
    cudaGetSymbolAddress((void**)&bsum,g_bsum);
    cudaGetSymbolAddress((void**)&deg_in,  g_deg_in);
    cudaGetSymbolAddress((void**)&deg_out, g_deg_out);
    cudaGetSymbolAddress((void**)&rp_in,   g_rp_in);
    cudaGetSymbolAddress((void**)&rp_out,  g_rp_out);
    cudaGetSymbolAddress((void**)&cur_in,  g_cur_in);
    cudaGetSymbolAddress((void**)&cur_out, g_cur_out);
    cudaGetSymbolAddress((void**)&csrc_in, g_csrc_in);
    cudaGetSymbolAddress((void**)&csrc_out,g_csrc_out);
    cudaGetSymbolAddress((void**)&cw_in,   g_cw_in);
    cudaGetSymbolAddress((void**)&cw_out,  g_cw_out);

    const int N = NN, E = EE, TPB = 256;
    const int SMEM_BYTES = (128 * 132 + 2 * 16384) * 4;

    cudaFuncSetAttribute(tgemm_kernel<256>, cudaFuncAttributeMaxDynamicSharedMemorySize, SMEM_BYTES);
    cudaFuncSetAttribute(tgemm_kernel<192>, cudaFuncAttributeMaxDynamicSharedMemorySize, SMEM_BYTES);

    detect_kernel<<<1, 32>>>(ei_in);
    zero_deg_kernel<<<(N + TPB - 1) / TPB, TPB>>>(deg_in, deg_out, N);
    pe_kernel<<<(N * 128 + TPB - 1) / TPB, TPB>>>(x, pe, h0, N * 128);
    prep_kernel<<<(16384 + 12288 + 448 + TPB - 1) / TPB, TPB>>>(
        Wmi0, Wmo0, Ws0, Wmi1, Wmo1, Ws1, resW,
        bmi0, bsi0, bmo0, bso0, bmi1, bsi1, bmo1, bso1, resb,
        blob0, blob1, bsum);

    // CSR build for both edge sets
    count_kernel<<<(E + TPB - 1) / TPB, TPB>>>(ei_in,  deg_in,  E);
    count_kernel<<<(E + TPB - 1) / TPB, TPB>>>(ei_out, deg_out, E);
    scan_kernel<<<2, 1024>>>(deg_in, deg_out, rp_in, rp_out, cur_in, cur_out, N);
    scatter_kernel<<<(E + TPB - 1) / TPB, TPB>>>(ei_in,  ew_in,  cur_in,  csrc_in,  cw_in,  E);
    scatter_kernel<<<(E + TPB - 1) / TPB, TPB>>>(ei_out, ew_out, cur_out, csrc_out, cw_out, E);

    const int GBLK = (N + 127) / 128;

    // ---- layer 0: tensor GEMM (128 -> 256) then gather+combine ----
    tgemm_kernel<256><<<GBLK, 256, SMEM_BYTES>>>(h0, blob0, t, N);
    gather0_kernel<<<(N * 32 + TPB - 1) / TPB, TPB>>>(
        t, rp_in, csrc_in, cw_in, rp_out, csrc_out, cw_out,
        bsum, cin0, cout0, h0, h1, N);

    // ---- layer 1: tensor GEMM (128 -> 192, incl residual proj) ----
    tgemm_kernel<192><<<GBLK, 256, SMEM_BYTES>>>(h1, blob1, u, N);
    gather1_kernel<<<(N * 32 + TPB - 1) / TPB, TPB>>>(
        u, rp_in, csrc_in, cw_in, rp_out, csrc_out, cw_out,
        bsum, cin1, cout1, h2, N);

    // ---- decoder + log_softmax + emb ----
    float* out = (float*)d_out;
    decoder_kernel<<<(N + 15) / 16, 256>>>(h2, decW, decb, out, out + (size_t)N * CLS, N);
}

// round 4
// speedup vs baseline: 2.5889x; 1.1433x over previous
#include <cuda_runtime.h>
#include <math.h>

#define NN 50000
#define EE 800000
#define CLS 128

// ---------------- static device scratch ----------------
__device__ float g_t [NN * 256];
__device__ float g_u [NN * 192];
__device__ float g_h1[NN * 128];
__device__ float g_h2[NN * 64];
__device__ float4 g_blob0[16384];   // layer0 weights K=128,N=256, frag order, hi/lo
__device__ float4 g_blob1[12288];   // layer1 weights K=128,N=192 (incl res), frag order
__device__ float g_bsum[448];
__device__ int   g_deg_in[NN];
__device__ int   g_deg_out[NN];
__device__ int   g_rp_in[NN + 1];
__device__ int   g_rp_out[NN + 1];
__device__ int   g_cur_in[NN];
__device__ int   g_cur_out[NN];
__device__ int   g_csrc_in[EE];
__device__ float g_cw_in[EE];
__device__ int   g_csrc_out[EE];
__device__ float g_cw_out[EE];
__device__ int   g_is64;

// ---------------- tf32 helpers ----------------
__device__ __forceinline__ void split_tf32(float a, unsigned& hi, unsigned& lo) {
    asm("cvt.rna.tf32.f32 %0, %1;" : "=r"(hi) : "f"(a));
    float r = a - __uint_as_float(hi);
    asm("cvt.rna.tf32.f32 %0, %1;" : "=r"(lo) : "f"(r));
}

__device__ __forceinline__ void mma_tf32(float4& d,
    unsigned a0, unsigned a1, unsigned a2, unsigned a3,
    unsigned b0, unsigned b1)
{
    asm volatile(
        "mma.sync.aligned.m16n8k8.row.col.f32.tf32.tf32.f32 "
        "{%0,%1,%2,%3},{%4,%5,%6,%7},{%8,%9},{%0,%1,%2,%3};"
        : "+f"(d.x), "+f"(d.y), "+f"(d.z), "+f"(d.w)
        : "r"(a0), "r"(a1), "r"(a2), "r"(a3), "r"(b0), "r"(b1));
}

__device__ __forceinline__ void cp16(void* smem_dst, const void* gsrc, int sz) {
    unsigned du = (unsigned)__cvta_generic_to_shared(smem_dst);
    asm volatile("cp.async.cg.shared.global [%0], [%1], 16, %2;"
                 :: "r"(du), "l"(gsrc), "r"(sz));
}

// ---------------- misc small kernels ----------------
__global__ void detect_kernel(const int* __restrict__ ei, int* __restrict__ da,
                              int* __restrict__ db, int n) {
    if (blockIdx.x == 0 && threadIdx.x == 0) {
        int z = 0;
        for (int i = 1; i < 129; i += 2) z |= ei[i];
        g_is64 = (z == 0) ? 1 : 0;
    }
    int i = blockIdx.x * blockDim.x + threadIdx.x;
    if (i < n) { da[i] = 0; db[i] = 0; }
}

// build frag-ordered, hi/lo-split weight blobs + combined biases
__global__ void prep_kernel(
    const float* __restrict__ Wmi0, const float* __restrict__ Wmo0, const float* __restrict__ Ws0,
    const float* __restrict__ Wmi1, const float* __restrict__ Wmo1, const float* __restrict__ Ws1,
    const float* __restrict__ resW,
    const float* __restrict__ bmi0, const float* __restrict__ bsi0,
    const float* __restrict__ bmo0, const float* __restrict__ bso0,
    const float* __restrict__ bmi1, const float* __restrict__ bsi1,
    const float* __restrict__ bmo1, const float* __restrict__ bso1,
    const float* __restrict__ resb,
    float4* __restrict__ blob0, float4* __restrict__ blob1, float* __restrict__ bsum)
{
    int i = blockIdx.x * blockDim.x + threadIdx.x;
    if (i < 16384) {
        int lane = i & 31; int j = i >> 5;
        int nt = j & 7; j >>= 3;
        int ks = j & 15; j >>= 4;
        int nc = j;
        int n = nc * 64 + nt * 8 + (lane >> 2);
        int ka = ks * 8 + (lane & 3), kb = ka + 4;
        int nn = n & 127;
        float a = Ws0[ka * 128 + nn] + ((n < 128) ? Wmi0[ka * 128 + n] : Wmo0[ka * 128 + n - 128]);
        float b = Ws0[kb * 128 + nn] + ((n < 128) ? Wmi0[kb * 128 + n] : Wmo0[kb * 128 + n - 128]);
        unsigned ha, la, hb, lb;
        split_tf32(a, ha, la); split_tf32(b, hb, lb);
        blob0[i] = make_float4(__uint_as_float(ha), __uint_as_float(hb),
                               __uint_as_float(la), __uint_as_float(lb));
        return;
    }
    int i1 = i - 16384;
    if (i1 < 12288) {
        int lane = i1 & 31; int j = i1 >> 5;
        int nt = j & 7; j >>= 3;
        int ks = j & 15; j >>= 4;
        int nc = j;
        int n = nc * 64 + nt * 8 + (lane >> 2);
        int ka = ks * 8 + (lane & 3), kb = ka + 4;
        float a, b;
        if (n < 128) {
            int nn = n & 63;
            a = Ws1[ka * 64 + nn] + ((n < 64) ? Wmi1[ka * 64 + n] : Wmo1[ka * 64 + n - 64]);
            b = Ws1[kb * 64 + nn] + ((n < 64) ? Wmi1[kb * 64 + n] : Wmo1[kb * 64 + n - 64]);
        } else {
            a = resW[ka * 64 + n - 128];
            b = resW[kb * 64 + n - 128];
        }
        unsigned ha, la, hb, lb;
        split_tf32(a, ha, la); split_tf32(b, hb, lb);
        blob1[i1] = make_float4(__uint_as_float(ha), __uint_as_float(hb),
                                __uint_as_float(la), __uint_as_float(lb));
        return;
    }
    int i2 = i1 - 12288;
    if (i2 < 128)       bsum[i2] = bmi0[i2] + bsi0[i2];
    else if (i2 < 256)  bsum[i2] = bmo0[i2 - 128] + bso0[i2 - 128];
    else if (i2 < 320)  bsum[i2] = bmi1[i2 - 256] + bsi1[i2 - 256];
    else if (i2 < 384)  bsum[i2] = bmo1[i2 - 320] + bso1[i2 - 320];
    else if (i2 < 448)  bsum[i2] = resb[i2 - 384];
}

// ---------------- CSR build (fused dual) ----------------
__global__ void count_dual_kernel(const int* __restrict__ ei_a, const int* __restrict__ ei_b,
                                  int* __restrict__ deg_a, int* __restrict__ deg_b, int E)
{
    int e = blockIdx.x * blockDim.x + threadIdx.x;
    int which = (e >= E);
    int idx = which ? e - E : e;
    if (idx >= E) return;
    const int* ei = which ? ei_b : ei_a;
    int* deg = which ? deg_b : deg_a;
    int tgt;
    if (g_is64) tgt = (int)((const long long*)ei)[E + idx];
    else        tgt = ei[E + idx];
    atomicAdd(deg + tgt, 1);
}

__global__ __launch_bounds__(1024) void scan_kernel(
    const int* __restrict__ deg_in, const int* __restrict__ deg_out,
    int* __restrict__ rp_in, int* __restrict__ rp_out,
    int* __restrict__ cur_in, int* __restrict__ cur_out, int n)
{
    const int* deg = blockIdx.x ? deg_out : deg_in;
    int* rp  = blockIdx.x ? rp_out  : rp_in;
    int* cur = blockIdx.x ? cur_out : cur_in;
    __shared__ int wsum[32];
    int tid = threadIdx.x, lane = tid & 31, wid = tid >> 5;
    int carry = 0;
    for (int base = 0; base < n; base += 1024) {
        int i = base + tid;
        int x = (i < n) ? deg[i] : 0;
        int v = x;
#pragma unroll
        for (int off = 1; off < 32; off <<= 1) {
            int t = __shfl_up_sync(0xffffffffu, v, off);
            if (lane >= off) v += t;
        }
        if (lane == 31) wsum[wid] = v;
        __syncthreads();
        if (wid == 0) {
            int w = wsum[lane];
#pragma unroll
            for (int off = 1; off < 32; off <<= 1) {
                int t = __shfl_up_sync(0xffffffffu, w, off);
                if (lane >= off) w += t;
            }
            wsum[lane] = w;
        }
        __syncthreads();
        int woff = wid ? wsum[wid - 1] : 0;
        int total = wsum[31];
        if (i < n) {
            int excl = carry + woff + v - x;
            rp[i] = excl;
            cur[i] = excl;
        }
        carry += total;
        __syncthreads();
    }
    if (tid == 0) rp[n] = carry;
}

__global__ void scatter_dual_kernel(
    const int* __restrict__ ei_a, const float* __restrict__ ew_a,
    const int* __restrict__ ei_b, const float* __restrict__ ew_b,
    int* __restrict__ cur_a, int* __restrict__ cur_b,
    int* __restrict__ csrc_a, int* __restrict__ csrc_b,
    float* __restrict__ cw_a, float* __restrict__ cw_b, int E)
{
    int e = blockIdx.x * blockDim.x + threadIdx.x;
    int which = (e >= E);
    int idx = which ? e - E : e;
    if (idx >= E) return;
    const int* ei   = which ? ei_b : ei_a;
    const float* ew = which ? ew_b : ew_a;
    int* cur  = which ? cur_b : cur_a;
    int* csrc = which ? csrc_b : csrc_a;
    float* cw = which ? cw_b : cw_a;
    int src, tgt;
    if (g_is64) {
        const long long* p = (const long long*)ei;
        src = (int)p[idx]; tgt = (int)p[E + idx];
    } else {
        src = ei[idx]; tgt = ei[E + idx];
    }
    int pos = atomicAdd(cur + tgt, 1);
    csrc[pos] = src;
    cw[pos]   = ew[idx];
}

// ---------------- tensor-core GEMM: out[M x N] = (H (+pe)) @ W ------------
template<int N, bool ADD_PE>
__global__ __launch_bounds__(256) void tgemm_kernel(
    const float* __restrict__ H, const float* __restrict__ pe,
    const float4* __restrict__ Wblob, float* __restrict__ out, int nrows)
{
    constexpr int K = 128;
    constexpr int CHUNKS = N / 64;
    constexpr int AST = K + 4;
    extern __shared__ float smem[];
    float* shA  = smem;
    float* shB0 = smem + 128 * AST;
    float* shB1 = shB0 + 16384;

    const int tid  = threadIdx.x;
    const int lane = tid & 31;
    const int wm   = (tid >> 5) * 16;
    const int g    = lane >> 2;
    const int row0 = blockIdx.x * 128;

#pragma unroll
    for (int i = 0; i < 16; i++) {
        int lin = tid + 256 * i;
        int r = lin >> 5, c4 = (lin & 31) << 2;
        int sz = (row0 + r < nrows) ? 16 : 0;
        cp16(shA + r * AST + c4, H + (size_t)(row0 + r) * K + c4, sz);
    }
#pragma unroll
    for (int i = 0; i < 16; i++) {
        int lin = tid + 256 * i;
        cp16(shB0 + lin * 4, Wblob + lin, 16);
    }
    asm volatile("cp.async.commit_group;");
    asm volatile("cp.async.wait_group 0;");
    __syncthreads();

    if (ADD_PE) {
        int c4 = (tid & 31) << 2;
        float4 pv = *reinterpret_cast<const float4*>(pe + c4);
#pragma unroll
        for (int i = 0; i < 16; i++) {
            int r = (tid + 256 * i) >> 5;
            float4 v = *reinterpret_cast<float4*>(shA + r * AST + c4);
            v.x += pv.x; v.y += pv.y; v.z += pv.z; v.w += pv.w;
            *reinterpret_cast<float4*>(shA + r * AST + c4) = v;
        }
        __syncthreads();
    }

    for (int c = 0; c < CHUNKS; c++) {
        if (c + 1 < CHUNKS) {
            float* nb = ((c + 1) & 1) ? shB1 : shB0;
            const float4* src = Wblob + (size_t)(c + 1) * 4096;
#pragma unroll
            for (int i = 0; i < 16; i++) {
                int lin = tid + 256 * i;
                cp16(nb + lin * 4, src + lin, 16);
            }
            asm volatile("cp.async.commit_group;");
        }

        const float* shB = (c & 1) ? shB1 : shB0;
        float4 acc[8];
#pragma unroll
        for (int nt = 0; nt < 8; nt++) acc[nt] = make_float4(0.f, 0.f, 0.f, 0.f);

#pragma unroll 2
        for (int ks = 0; ks < 16; ks++) {
            int ka = ks * 8 + (lane & 3);
            const float* ap = shA + (wm + g) * AST + ka;
            float a0 = ap[0], a2 = ap[4];
            float a1 = ap[8 * AST], a3 = ap[8 * AST + 4];
            unsigned h0, l0, h1, l1, h2, l2, h3, l3;
            split_tf32(a0, h0, l0); split_tf32(a1, h1, l1);
            split_tf32(a2, h2, l2); split_tf32(a3, h3, l3);
            const uint4* bp = reinterpret_cast<const uint4*>(shB) + ks * 256 + lane;
#pragma unroll
            for (int nt = 0; nt < 8; nt++) {
                uint4 b = bp[nt * 32];
                mma_tf32(acc[nt], h0, h1, h2, h3, b.x, b.y);
                mma_tf32(acc[nt], h0, h1, h2, h3, b.z, b.w);
                mma_tf32(acc[nt], l0, l1, l2, l3, b.x, b.y);
            }
        }

        int r1 = row0 + wm + g, r2 = r1 + 8;
        int colb = c * 64 + 2 * (lane & 3);
#pragma unroll
        for (int nt = 0; nt < 8; nt++) {
            int col = colb + nt * 8;
            if (r1 < nrows)
                *reinterpret_cast<float2*>(out + (size_t)r1 * N + col) = make_float2(acc[nt].x, acc[nt].y);
            if (r2 < nrows)
                *reinterpret_cast<float2*>(out + (size_t)r2 * N + col) = make_float2(acc[nt].z, acc[nt].w);
        }

        asm volatile("cp.async.wait_group 0;");
        __syncthreads();
    }
}

// ---------------- layer-0 gather+combine: warp per node --------------------
__global__ __launch_bounds__(256) void gather0_kernel(
    const float* __restrict__ t,
    const int* __restrict__ rpi, const int* __restrict__ si, const float* __restrict__ wi,
    const int* __restrict__ rpo, const int* __restrict__ so, const float* __restrict__ wo,
    const float* __restrict__ bsum,
    const float* __restrict__ cin, const float* __restrict__ cout,
    const float* __restrict__ x, const float* __restrict__ pe,
    float* __restrict__ h1, int n)
{
    int node = (blockIdx.x * 256 + threadIdx.x) >> 5;
    int lane = threadIdx.x & 31;
    if (node >= n) return;

    float4 ic = make_float4(0.f, 0.f, 0.f, 0.f);
    float4 oc = make_float4(0.f, 0.f, 0.f, 0.f);

    int s = rpi[node], e = rpi[node + 1];
#pragma unroll 4
    for (int k = s; k < e; k++) {
        int   src = __ldg(si + k);
        float w   = __ldg(wi + k);
        float4 v = *reinterpret_cast<const float4*>(t + (size_t)src * 256 + lane * 4);
        ic.x += w * v.x; ic.y += w * v.y; ic.z += w * v.z; ic.w += w * v.w;
    }
    s = rpo[node]; e = rpo[node + 1];
#pragma unroll 4
    for (int k = s; k < e; k++) {
        int   src = __ldg(so + k);
        float w   = __ldg(wo + k);
        float4 v = *reinterpret_cast<const float4*>(t + (size_t)src * 256 + 128 + lane * 4);
        oc.x += w * v.x; oc.y += w * v.y; oc.z += w * v.z; oc.w += w * v.w;
    }

    float ci = __ldg(cin + node), co = __ldg(cout + node);
    float4 bi = *reinterpret_cast<const float4*>(bsum + lane * 4);
    float4 bo = *reinterpret_cast<const float4*>(bsum + 128 + lane * 4);
    float4 r  = *reinterpret_cast<const float4*>(x + (size_t)node * 128 + lane * 4);
    float4 pv = *reinterpret_cast<const float4*>(pe + lane * 4);
    r.x += pv.x; r.y += pv.y; r.z += pv.z; r.w += pv.w;
    float4 o;
    o.x = tanhf(ci * (ic.x + bi.x) + co * (oc.x + bo.x) + r.x);
    o.y = tanhf(ci * (ic.y + bi.y) + co * (oc.y + bo.y) + r.y);
    o.z = tanhf(ci * (ic.z + bi.z) + co * (oc.z + bo.z) + r.z);
    o.w = tanhf(ci * (ic.w + bi.w) + co * (oc.w + bo.w) + r.w);
    *reinterpret_cast<float4*>(h1 + (size_t)node * 128 + lane * 4) = o;
}

// ---------------- layer-1 gather+combine (u stride 192, res in cols 128+) --
__global__ __launch_bounds__(256) void gather1_kernel(
    const float* __restrict__ u,
    const int* __restrict__ rpi, const int* __restrict__ si, const float* __restrict__ wi,
    const int* __restrict__ rpo, const int* __restrict__ so, const float* __restrict__ wo,
    const float* __restrict__ bsum,
    const float* __restrict__ cin, const float* __restrict__ cout,
    float* __restrict__ h2, int n)
{
    int node = (blockIdx.x * 256 + threadIdx.x) >> 5;
    int lane = threadIdx.x & 31;
    if (node >= n) return;

    float2 ic = make_float2(0.f, 0.f);
    float2 oc = make_float2(0.f, 0.f);

    int s = rpi[node], e = rpi[node + 1];
#pragma unroll 4
    for (int k = s; k < e; k++) {
        int   src = __ldg(si + k);
        float w   = __ldg(wi + k);
        float2 v = *reinterpret_cast<const float2*>(u + (size_t)src * 192 + lane * 2);
        ic.x += w * v.x; ic.y += w * v.y;
    }
    s = rpo[node]; e = rpo[node + 1];
#pragma unroll 4
    for (int k = s; k < e; k++) {
        int   src = __ldg(so + k);
        float w   = __ldg(wo + k);
        float2 v = *reinterpret_cast<const float2*>(u + (size_t)src * 192 + 64 + lane * 2);
        oc.x += w * v.x; oc.y += w * v.y;
    }

    float ci = __ldg(cin + node), co = __ldg(cout + node);
    float2 bi = *reinterpret_cast<const float2*>(bsum + 256 + lane * 2);
    float2 bo = *reinterpret_cast<const float2*>(bsum + 320 + lane * 2);
    float2 rb = *reinterpret_cast<const float2*>(bsum + 384 + lane * 2);
    float2 r  = *reinterpret_cast<const float2*>(u + (size_t)node * 192 + 128 + lane * 2);
    float2 o;
    o.x = tanhf(ci * (ic.x + bi.x) + co * (oc.x + bo.x) + r.x + rb.x);
    o.y = tanhf(ci * (ic.y + bi.y) + co * (oc.y + bo.y) + r.y + rb.y);
    *reinterpret_cast<float2*>(h2 + (size_t)node * 64 + lane * 2) = o;
}

// ---------------- decoder: warp handles 2 nodes -----------------------------
__device__ __forceinline__ void logsm_store(float4 acc, int node, int lane,
                                            float* __restrict__ logp, int n) {
    float m = fmaxf(fmaxf(acc.x, acc.y), fmaxf(acc.z, acc.w));
#pragma unroll
    for (int off = 16; off > 0; off >>= 1)
        m = fmaxf(m, __shfl_xor_sync(0xffffffffu, m, off));
    float s = expf(acc.x - m) + expf(acc.y - m) + expf(acc.z - m) + expf(acc.w - m);
#pragma unroll
    for (int off = 16; off > 0; off >>= 1)
        s += __shfl_xor_sync(0xffffffffu, s, off);
    float lse = m + logf(s);
    if (node < n) {
        float4 o = make_float4(acc.x - lse, acc.y - lse, acc.z - lse, acc.w - lse);
        *reinterpret_cast<float4*>(logp + (size_t)node * CLS + lane * 4) = o;
    }
}

__device__ __forceinline__ void emb_store(const float* __restrict__ h, int node, int lane,
                                          float* __restrict__ emb, int n) {
    float2 v = *reinterpret_cast<const float2*>(h + lane * 2);
    float sq = v.x * v.x + v.y * v.y;
#pragma unroll
    for (int off = 16; off > 0; off >>= 1)
        sq += __shfl_xor_sync(0xffffffffu, sq, off);
    float inv = 1.f / (sqrtf(sq) + 1e-12f);
    if (node < n) {
        float2 o = make_float2(v.x * inv, v.y * inv);
        *reinterpret_cast<float2*>(emb + (size_t)node * 64 + lane * 2) = o;
    }
}

__global__ __launch_bounds__(256) void decoder_kernel(
    const float* __restrict__ h2, const float* __restrict__ W,
    const float* __restrict__ b, float* __restrict__ logp,
    float* __restrict__ emb, int n)
{
    __shared__ float sh[16 * 64];
    int tid = threadIdx.x;
    int node0 = blockIdx.x * 16;

    for (int i = tid; i < 16 * 64; i += 256) {
        int nd = node0 + (i >> 6);
        sh[i] = (nd < n) ? h2[(size_t)nd * 64 + (i & 63)] : 0.f;
    }
    __syncthreads();

    int wid = tid >> 5, lane = tid & 31;
    int la = wid * 2, lb = la + 1;
    const float* ha = sh + la * 64;
    const float* hb = sh + lb * 64;

    float4 bj = *reinterpret_cast<const float4*>(b + lane * 4);
    float4 acc0 = bj, acc1 = bj;

#pragma unroll 4
    for (int k = 0; k < 64; k++) {
        float4 w = *reinterpret_cast<const float4*>(W + (size_t)k * CLS + lane * 4);
        float a = ha[k], c = hb[k];
        acc0.x += a * w.x; acc0.y += a * w.y; acc0.z += a * w.z; acc0.w += a * w.w;
        acc1.x += c * w.x; acc1.y += c * w.y; acc1.z += c * w.z; acc1.w += c * w.w;
    }

    logsm_store(acc0, node0 + la, lane, logp, n);
    logsm_store(acc1, node0 + lb, lane, logp, n);
    emb_store(ha, node0 + la, lane, emb, n);
    emb_store(hb, node0 + lb, lane, emb, n);
}

// ---------------- host ----------------
extern "C" void kernel_launch(void* const* d_in, const int* in_sizes, int n_in,
                              void* d_out, int out_size)
{
    const float* x      = (const float*)d_in[0];
    const int*   ei_in  = (const int*)d_in[1];
    const float* ew_in  = (const float*)d_in[2];
    const int*   ei_out = (const int*)d_in[3];
    const float* ew_out = (const float*)d_in[4];
    const float* pe     = (const float*)d_in[5];

    const float* Wmi0 = (const float*)d_in[6];
    const float* Wmo0 = (const float*)d_in[7];
    const float* Ws0  = (const float*)d_in[8];
    const float* bmi0 = (const float*)d_in[9];
    const float* bmo0 = (const float*)d_in[10];
    const float* bsi0 = (const float*)d_in[11];
    const float* bso0 = (const float*)d_in[12];
    const float* cin0 = (const float*)d_in[13];
    const float* cout0= (const float*)d_in[14];

    const float* Wmi1 = (const float*)d_in[15];
    const float* Wmo1 = (const float*)d_in[16];
    const float* Ws1  = (const float*)d_in[17];
    const float* bmi1 = (const float*)d_in[18];
    const float* bmo1 = (const float*)d_in[19];
    const float* bsi1 = (const float*)d_in[20];
    const float* bso1 = (const float*)d_in[21];
    const float* cin1 = (const float*)d_in[22];
    const float* cout1= (const float*)d_in[23];

    const float* resW = (const float*)d_in[24];
    const float* resb = (const float*)d_in[25];
    const float* decW = (const float*)d_in[26];
    const float* decb = (const float*)d_in[27];

    float *t, *u, *h1, *h2, *bsum;
    float4 *blob0, *blob1;
    float *cw_in, *cw_out;
    int *deg_in, *deg_out, *rp_in, *rp_out, *cur_in, *cur_out, *csrc_in, *csrc_out;
    cudaGetSymbolAddress((void**)&t,   g_t);
    cudaGetSymbolAddress((void**)&u,   g_u);
    cudaGetSymbolAddress((void**)&h1,  g_h1);
    cudaGetSymbolAddress((void**)&h2,  g_h2);
    cudaGetSymbolAddress((void**)&blob0, g_blob0);
    cudaGetSymbolAddress((void**)&blob1, g_blob1);
    cudaGetSymbolAddress((void**)&bsum,g_bsum);
    cudaGetSymbolAddress((void**)&deg_in,  g_deg_in);
    cudaGetSymbolAddress((void**)&deg_out, g_deg_out);
    cudaGetSymbolAddress((void**)&rp_in,   g_rp_in);
    cudaGetSymbolAddress((void**)&rp_out,  g_rp_out);
    cudaGetSymbolAddress((void**)&cur_in,  g_cur_in);
    cudaGetSymbolAddress((void**)&cur_out, g_cur_out);
    cudaGetSymbolAddress((void**)&csrc_in, g_csrc_in);
    cudaGetSymbolAddress((void**)&csrc_out,g_csrc_out);
    cudaGetSymbolAddress((void**)&cw_in,   g_cw_in);
    cudaGetSymbolAddress((void**)&cw_out,  g_cw_out);

    const int N = NN, E = EE, TPB = 256;
    const int SMEM_BYTES = (128 * 132 + 2 * 16384) * 4;

    static cudaStream_t s2 = nullptr;
    static cudaEvent_t ev0 = nullptr, ev2 = nullptr;
    if (!s2) {
        cudaStreamCreateWithFlags(&s2, cudaStreamNonBlocking);
        cudaEventCreateWithFlags(&ev0, cudaEventDisableTiming);
        cudaEventCreateWithFlags(&ev2, cudaEventDisableTiming);
        cudaFuncSetAttribute((const void*)tgemm_kernel<256, true>,
                             cudaFuncAttributeMaxDynamicSharedMemorySize, SMEM_BYTES);
        cudaFuncSetAttribute((const void*)tgemm_kernel<192, false>,
                             cudaFuncAttributeMaxDynamicSharedMemorySize, SMEM_BYTES);
    }

    // main stream: detect+zero, then fork CSR branch onto s2
    detect_kernel<<<(N + TPB - 1) / TPB, TPB>>>(ei_in, deg_in, deg_out, N);
    cudaEventRecord(ev0, 0);

    // CSR branch (stream s2), runs concurrently with prep + tgemm0
    cudaStreamWaitEvent(s2, ev0, 0);
    count_dual_kernel<<<(2 * E + TPB - 1) / TPB, TPB, 0, s2>>>(ei_in, ei_out, deg_in, deg_out, E);
    scan_kernel<<<2, 1024, 0, s2>>>(deg_in, deg_out, rp_in, rp_out, cur_in, cur_out, N);
    scatter_dual_kernel<<<(2 * E + TPB - 1) / TPB, TPB, 0, s2>>>(
        ei_in, ew_in, ei_out, ew_out, cur_in, cur_out,
        csrc_in, csrc_out, cw_in, cw_out, E);
    cudaEventRecord(ev2, s2);

    // main branch: weight prep + layer-0 GEMM (PE folded into A staging)
    prep_kernel<<<(16384 + 12288 + 448 + TPB - 1) / TPB, TPB>>>(
        Wmi0, Wmo0, Ws0, Wmi1, Wmo1, Ws1, resW,
        bmi0, bsi0, bmo0, bso0, bmi1, bsi1, bmo1, bso1, resb,
        blob0, blob1, bsum);

    const int GBLK = (N + 127) / 128;
    tgemm_kernel<256, true><<<GBLK, 256, SMEM_BYTES>>>(x, pe, blob0, t, N);

    // join: gather0 needs both CSR and t
    cudaStreamWaitEvent(0, ev2, 0);
    gather0_kernel<<<(N * 32 + TPB - 1) / TPB, TPB>>>(
        t, rp_in, csrc_in, cw_in, rp_out, csrc_out, cw_out,
        bsum, cin0, cout0, x, pe, h1, N);

    // layer 1
    tgemm_kernel<192, false><<<GBLK, 256, SMEM_BYTES>>>(h1, pe, blob1, u, N);
    gather1_kernel<<<(N * 32 + TPB - 1) / TPB, TPB>>>(
        u, rp_in, csrc_in, cw_in, rp_out, csrc_out, cw_out,
        bsum, cin1, cout1, h2, N);

    // decoder + log_softmax + emb
    float* out = (float*)d_out;
    decoder_kernel<<<(N + 15) / 16, 256>>>(h2, decW, decb, out, out + (size_t)N * CLS, N);
}

// round 5
// speedup vs baseline: 2.7293x; 1.0542x over previous
#include <cuda_runtime.h>
#include <cuda_fp16.h>
#include <math.h>

#define NN 50000
#define EE 800000
#define CLS 128

// ---------------- static device scratch ----------------
__device__ __half g_t [NN * 256];
__device__ __half g_u [NN * 192];
__device__ float g_h1[NN * 128];
__device__ float g_h2[NN * 64];
__device__ float4 g_blob0[16384];   // layer0 weights K=128,N=256, frag order, hi/lo
__device__ float4 g_blob1[12288];   // layer1 weights K=128,N=192 (incl res), frag order
__device__ float g_bsum[448];
__device__ int   g_deg_in[NN];
__device__ int   g_deg_out[NN];
__device__ int   g_rp_in[NN + 1];
__device__ int   g_rp_out[NN + 1];
__device__ int   g_cur_in[NN];
__device__ int   g_cur_out[NN];
__device__ int2  g_edge_in[EE];     // packed (src, weight bits)
__device__ int2  g_edge_out[EE];
__device__ int   g_is64;

// ---------------- tf32 helpers ----------------
__device__ __forceinline__ void split_tf32(float a, unsigned& hi, unsigned& lo) {
    asm("cvt.rna.tf32.f32 %0, %1;" : "=r"(hi) : "f"(a));
    float r = a - __uint_as_float(hi);
    asm("cvt.rna.tf32.f32 %0, %1;" : "=r"(lo) : "f"(r));
}

__device__ __forceinline__ void mma_tf32(float4& d,
    unsigned a0, unsigned a1, unsigned a2, unsigned a3,
    unsigned b0, unsigned b1)
{
    asm volatile(
        "mma.sync.aligned.m16n8k8.row.col.f32.tf32.tf32.f32 "
        "{%0,%1,%2,%3},{%4,%5,%6,%7},{%8,%9},{%0,%1,%2,%3};"
        : "+f"(d.x), "+f"(d.y), "+f"(d.z), "+f"(d.w)
        : "r"(a0), "r"(a1), "r"(a2), "r"(a3), "r"(b0), "r"(b1));
}

__device__ __forceinline__ void cp16(void* smem_dst, const void* gsrc, int sz) {
    unsigned du = (unsigned)__cvta_generic_to_shared(smem_dst);
    asm volatile("cp.async.cg.shared.global [%0], [%1], 16, %2;"
                 :: "r"(du), "l"(gsrc), "r"(sz));
}

// ---------------- misc small kernels ----------------
__global__ void detect_kernel(const int* __restrict__ ei, int* __restrict__ da,
                              int* __restrict__ db, int n) {
    if (blockIdx.x == 0 && threadIdx.x == 0) {
        int z = 0;
        for (int i = 1; i < 129; i += 2) z |= ei[i];
        g_is64 = (z == 0) ? 1 : 0;
    }
    int i = blockIdx.x * blockDim.x + threadIdx.x;
    if (i < n) { da[i] = 0; db[i] = 0; }
}

// build frag-ordered, hi/lo-split weight blobs + combined biases
__global__ void prep_kernel(
    const float* __restrict__ Wmi0, const float* __restrict__ Wmo0, const float* __restrict__ Ws0,
    const float* __restrict__ Wmi1, const float* __restrict__ Wmo1, const float* __restrict__ Ws1,
    const float* __restrict__ resW,
    const float* __restrict__ bmi0, const float* __restrict__ bsi0,
    const float* __restrict__ bmo0, const float* __restrict__ bso0,
    const float* __restrict__ bmi1, const float* __restrict__ bsi1,
    const float* __restrict__ bmo1, const float* __restrict__ bso1,
    const float* __restrict__ resb,
    float4* __restrict__ blob0, float4* __restrict__ blob1, float* __restrict__ bsum)
{
    int i = blockIdx.x * blockDim.x + threadIdx.x;
    if (i < 16384) {
        int lane = i & 31; int j = i >> 5;
        int nt = j & 7; j >>= 3;
        int ks = j & 15; j >>= 4;
        int nc = j;
        int n = nc * 64 + nt * 8 + (lane >> 2);
        int ka = ks * 8 + (lane & 3), kb = ka + 4;
        int nn = n & 127;
        float a = Ws0[ka * 128 + nn] + ((n < 128) ? Wmi0[ka * 128 + n] : Wmo0[ka * 128 + n - 128]);
        float b = Ws0[kb * 128 + nn] + ((n < 128) ? Wmi0[kb * 128 + n] : Wmo0[kb * 128 + n - 128]);
        unsigned ha, la, hb, lb;
        split_tf32(a, ha, la); split_tf32(b, hb, lb);
        blob0[i] = make_float4(__uint_as_float(ha), __uint_as_float(hb),
                               __uint_as_float(la), __uint_as_float(lb));
        return;
    }
    int i1 = i - 16384;
    if (i1 < 12288) {
        int lane = i1 & 31; int j = i1 >> 5;
        int nt = j & 7; j >>= 3;
        int ks = j & 15; j >>= 4;
        int nc = j;
        int n = nc * 64 + nt * 8 + (lane >> 2);
        int ka = ks * 8 + (lane & 3), kb = ka + 4;
        float a, b;
        if (n < 128) {
            int nn = n & 63;
            a = Ws1[ka * 64 + nn] + ((n < 64) ? Wmi1[ka * 64 + n] : Wmo1[ka * 64 + n - 64]);
            b = Ws1[kb * 64 + nn] + ((n < 64) ? Wmi1[kb * 64 + n] : Wmo1[kb * 64 + n - 64]);
        } else {
            a = resW[ka * 64 + n - 128];
            b = resW[kb * 64 + n - 128];
        }
        unsigned ha, la, hb, lb;
        split_tf32(a, ha, la); split_tf32(b, hb, lb);
        blob1[i1] = make_float4(__uint_as_float(ha), __uint_as_float(hb),
                                __uint_as_float(la), __uint_as_float(lb));
        return;
    }
    int i2 = i1 - 12288;
    if (i2 < 128)       bsum[i2] = bmi0[i2] + bsi0[i2];
    else if (i2 < 256)  bsum[i2] = bmo0[i2 - 128] + bso0[i2 - 128];
    else if (i2 < 320)  bsum[i2] = bmi1[i2 - 256] + bsi1[i2 - 256];
    else if (i2 < 384)  bsum[i2] = bmo1[i2 - 320] + bso1[i2 - 320];
    else if (i2 < 448)  bsum[i2] = resb[i2 - 384];
}

// ---------------- CSR build (fused dual, packed int2 payload) ----------------
__global__ void count_dual_kernel(const int* __restrict__ ei_a, const int* __restrict__ ei_b,
                                  int* __restrict__ deg_a, int* __restrict__ deg_b, int E)
{
    int e = blockIdx.x * blockDim.x + threadIdx.x;
    int which = (e >= E);
    int idx = which ? e - E : e;
    if (idx >= E) return;
    const int* ei = which ? ei_b : ei_a;
    int* deg = which ? deg_b : deg_a;
    int tgt;
    if (g_is64) tgt = (int)((const long long*)ei)[E + idx];
    else        tgt = ei[E + idx];
    atomicAdd(deg + tgt, 1);
}

__global__ __launch_bounds__(1024) void scan_kernel(
    const int* __restrict__ deg_in, const int* __restrict__ deg_out,
    int* __restrict__ rp_in, int* __restrict__ rp_out,
    int* __restrict__ cur_in, int* __restrict__ cur_out, int n)
{
    const int* deg = blockIdx.x ? deg_out : deg_in;
    int* rp  = blockIdx.x ? rp_out  : rp_in;
    int* cur = blockIdx.x ? cur_out : cur_in;
    __shared__ int wsum[32];
    int tid = threadIdx.x, lane = tid & 31, wid = tid >> 5;
    int carry = 0;
    for (int base = 0; base < n; base += 1024) {
        int i = base + tid;
        int x = (i < n) ? deg[i] : 0;
        int v = x;
#pragma unroll
        for (int off = 1; off < 32; off <<= 1) {
            int t = __shfl_up_sync(0xffffffffu, v, off);
            if (lane >= off) v += t;
        }
        if (lane == 31) wsum[wid] = v;
        __syncthreads();
        if (wid == 0) {
            int w = wsum[lane];
#pragma unroll
            for (int off = 1; off < 32; off <<= 1) {
                int t = __shfl_up_sync(0xffffffffu, w, off);
                if (lane >= off) w += t;
            }
            wsum[lane] = w;
        }
        __syncthreads();
        int woff = wid ? wsum[wid - 1] : 0;
        int total = wsum[31];
        if (i < n) {
            int excl = carry + woff + v - x;
            rp[i] = excl;
            cur[i] = excl;
        }
        carry += total;
        __syncthreads();
    }
    if (tid == 0) rp[n] = carry;
}

__global__ void scatter_dual_kernel(
    const int* __restrict__ ei_a, const float* __restrict__ ew_a,
    const int* __restrict__ ei_b, const float* __restrict__ ew_b,
    int* __restrict__ cur_a, int* __restrict__ cur_b,
    int2* __restrict__ edge_a, int2* __restrict__ edge_b, int E)
{
    int e = blockIdx.x * blockDim.x + threadIdx.x;
    int which = (e >= E);
    int idx = which ? e - E : e;
    if (idx >= E) return;
    const int* ei   = which ? ei_b : ei_a;
    const float* ew = which ? ew_b : ew_a;
    int* cur   = which ? cur_b : cur_a;
    int2* edge = which ? edge_b : edge_a;
    int src, tgt;
    if (g_is64) {
        const long long* p = (const long long*)ei;
        src = (int)p[idx]; tgt = (int)p[E + idx];
    } else {
        src = ei[idx]; tgt = ei[E + idx];
    }
    int pos = atomicAdd(cur + tgt, 1);
    edge[pos] = make_int2(src, __float_as_int(ew[idx]));
}

// ---------------- tensor-core GEMM: outH[M x N] = (H (+pe)) @ W (fp16 out) --
template<int N, bool ADD_PE>
__global__ __launch_bounds__(256) void tgemm_kernel(
    const float* __restrict__ H, const float* __restrict__ pe,
    const float4* __restrict__ Wblob, __half* __restrict__ outH, int nrows)
{
    constexpr int K = 128;
    constexpr int CHUNKS = N / 64;
    constexpr int AST = K + 4;
    extern __shared__ float smem[];
    float* shA  = smem;
    float* shB0 = smem + 128 * AST;
    float* shB1 = shB0 + 16384;

    const int tid  = threadIdx.x;
    const int lane = tid & 31;
    const int wm   = (tid >> 5) * 16;
    const int g    = lane >> 2;
    const int row0 = blockIdx.x * 128;

#pragma unroll
    for (int i = 0; i < 16; i++) {
        int lin = tid + 256 * i;
        int r = lin >> 5, c4 = (lin & 31) << 2;
        int sz = (row0 + r < nrows) ? 16 : 0;
        cp16(shA + r * AST + c4, H + (size_t)(row0 + r) * K + c4, sz);
    }
#pragma unroll
    for (int i = 0; i < 16; i++) {
        int lin = tid + 256 * i;
        cp16(shB0 + lin * 4, Wblob + lin, 16);
    }
    asm volatile("cp.async.commit_group;");
    asm volatile("cp.async.wait_group 0;");
    __syncthreads();

    if (ADD_PE) {
        int c4 = (tid & 31) << 2;
        float4 pv = *reinterpret_cast<const float4*>(pe + c4);
#pragma unroll
        for (int i = 0; i < 16; i++) {
            int r = (tid + 256 * i) >> 5;
            float4 v = *reinterpret_cast<float4*>(shA + r * AST + c4);
            v.x += pv.x; v.y += pv.y; v.z += pv.z; v.w += pv.w;
            *reinterpret_cast<float4*>(shA + r * AST + c4) = v;
        }
        __syncthreads();
    }

    for (int c = 0; c < CHUNKS; c++) {
        if (c + 1 < CHUNKS) {
            float* nb = ((c + 1) & 1) ? shB1 : shB0;
            const float4* src = Wblob + (size_t)(c + 1) * 4096;
#pragma unroll
            for (int i = 0; i < 16; i++) {
                int lin = tid + 256 * i;
                cp16(nb + lin * 4, src + lin, 16);
            }
            asm volatile("cp.async.commit_group;");
        }

        const float* shB = (c & 1) ? shB1 : shB0;
        float4 acc[8];
#pragma unroll
        for (int nt = 0; nt < 8; nt++) acc[nt] = make_float4(0.f, 0.f, 0.f, 0.f);

#pragma unroll 2
        for (int ks = 0; ks < 16; ks++) {
            int ka = ks * 8 + (lane & 3);
            const float* ap = shA + (wm + g) * AST + ka;
            float a0 = ap[0], a2 = ap[4];
            float a1 = ap[8 * AST], a3 = ap[8 * AST + 4];
            unsigned h0, l0, h1, l1, h2, l2, h3, l3;
            split_tf32(a0, h0, l0); split_tf32(a1, h1, l1);
            split_tf32(a2, h2, l2); split_tf32(a3, h3, l3);
            const uint4* bp = reinterpret_cast<const uint4*>(shB) + ks * 256 + lane;
#pragma unroll
            for (int nt = 0; nt < 8; nt++) {
                uint4 b = bp[nt * 32];
                mma_tf32(acc[nt], h0, h1, h2, h3, b.x, b.y);
                mma_tf32(acc[nt], h0, h1, h2, h3, b.z, b.w);
                mma_tf32(acc[nt], l0, l1, l2, l3, b.x, b.y);
            }
        }

        int r1 = row0 + wm + g, r2 = r1 + 8;
        int colb = c * 64 + 2 * (lane & 3);
#pragma unroll
        for (int nt = 0; nt < 8; nt++) {
            int col = colb + nt * 8;
            if (r1 < nrows)
                *reinterpret_cast<__half2*>(outH + (size_t)r1 * N + col) =
                    __floats2half2_rn(acc[nt].x, acc[nt].y);
            if (r2 < nrows)
                *reinterpret_cast<__half2*>(outH + (size_t)r2 * N + col) =
                    __floats2half2_rn(acc[nt].z, acc[nt].w);
        }

        asm volatile("cp.async.wait_group 0;");
        __syncthreads();
    }
}

// ---------------- layer-0 gather+combine: warp per node (fp16 t) -----------
__global__ __launch_bounds__(256) void gather0_kernel(
    const __half* __restrict__ t,
    const int* __restrict__ rpi, const int2* __restrict__ egi,
    const int* __restrict__ rpo, const int2* __restrict__ ego,
    const float* __restrict__ bsum,
    const float* __restrict__ cin, const float* __restrict__ cout,
    const float* __restrict__ x, const float* __restrict__ pe,
    float* __restrict__ h1, int n)
{
    int node = (blockIdx.x * 256 + threadIdx.x) >> 5;
    int lane = threadIdx.x & 31;
    if (node >= n) return;

    float4 ic = make_float4(0.f, 0.f, 0.f, 0.f);
    float4 oc = make_float4(0.f, 0.f, 0.f, 0.f);

    int s = rpi[node], e = rpi[node + 1];
#pragma unroll 4
    for (int k = s; k < e; k++) {
        int2 ed = __ldg(egi + k);
        float w = __int_as_float(ed.y);
        float2 raw = *reinterpret_cast<const float2*>(t + (size_t)ed.x * 256 + lane * 4);
        float2 a = __half22float2(*reinterpret_cast<const __half2*>(&raw.x));
        float2 b = __half22float2(*reinterpret_cast<const __half2*>(&raw.y));
        ic.x += w * a.x; ic.y += w * a.y; ic.z += w * b.x; ic.w += w * b.y;
    }
    s = rpo[node]; e = rpo[node + 1];
#pragma unroll 4
    for (int k = s; k < e; k++) {
        int2 ed = __ldg(ego + k);
        float w = __int_as_float(ed.y);
        float2 raw = *reinterpret_cast<const float2*>(t + (size_t)ed.x * 256 + 128 + lane * 4);
        float2 a = __half22float2(*reinterpret_cast<const __half2*>(&raw.x));
        float2 b = __half22float2(*reinterpret_cast<const __half2*>(&raw.y));
        oc.x += w * a.x; oc.y += w * a.y; oc.z += w * b.x; oc.w += w * b.y;
    }

    float ci = __ldg(cin + node), co = __ldg(cout + node);
    float4 bi = *reinterpret_cast<const float4*>(bsum + lane * 4);
    float4 bo = *reinterpret_cast<const float4*>(bsum + 128 + lane * 4);
    float4 r  = *reinterpret_cast<const float4*>(x + (size_t)node * 128 + lane * 4);
    float4 pv = *reinterpret_cast<const float4*>(pe + lane * 4);
    r.x += pv.x; r.y += pv.y; r.z += pv.z; r.w += pv.w;
    float4 o;
    o.x = tanhf(ci * (ic.x + bi.x) + co * (oc.x + bo.x) + r.x);
    o.y = tanhf(ci * (ic.y + bi.y) + co * (oc.y + bo.y) + r.y);
    o.z = tanhf(ci * (ic.z + bi.z) + co * (oc.z + bo.z) + r.z);
    o.w = tanhf(ci * (ic.w + bi.w) + co * (oc.w + bo.w) + r.w);
    *reinterpret_cast<float4*>(h1 + (size_t)node * 128 + lane * 4) = o;
}

// ---------------- layer-1 gather+combine (fp16 u, stride 192) --------------
__global__ __launch_bounds__(256) void gather1_kernel(
    const __half* __restrict__ u,
    const int* __restrict__ rpi, const int2* __restrict__ egi,
    const int* __restrict__ rpo, const int2* __restrict__ ego,
    const float* __restrict__ bsum,
    const float* __restrict__ cin, const float* __restrict__ cout,
    float* __restrict__ h2, int n)
{
    int node = (blockIdx.x * 256 + threadIdx.x) >> 5;
    int lane = threadIdx.x & 31;
    if (node >= n) return;

    float2 ic = make_float2(0.f, 0.f);
    float2 oc = make_float2(0.f, 0.f);

    int s = rpi[node], e = rpi[node + 1];
#pragma unroll 4
    for (int k = s; k < e; k++) {
        int2 ed = __ldg(egi + k);
        float w = __int_as_float(ed.y);
        float2 v = __half22float2(*reinterpret_cast<const __half2*>(u + (size_t)ed.x * 192 + lane * 2));
        ic.x += w * v.x; ic.y += w * v.y;
    }
    s = rpo[node]; e = rpo[node + 1];
#pragma unroll 4
    for (int k = s; k < e; k++) {
        int2 ed = __ldg(ego + k);
        float w = __int_as_float(ed.y);
        float2 v = __half22float2(*reinterpret_cast<const __half2*>(u + (size_t)ed.x * 192 + 64 + lane * 2));
        oc.x += w * v.x; oc.y += w * v.y;
    }

    float ci = __ldg(cin + node), co = __ldg(cout + node);
    float2 bi = *reinterpret_cast<const float2*>(bsum + 256 + lane * 2);
    float2 bo = *reinterpret_cast<const float2*>(bsum + 320 + lane * 2);
    float2 rb = *reinterpret_cast<const float2*>(bsum + 384 + lane * 2);
    float2 r  = __half22float2(*reinterpret_cast<const __half2*>(u + (size_t)node * 192 + 128 + lane * 2));
    float2 o;
    o.x = tanhf(ci * (ic.x + bi.x) + co * (oc.x + bo.x) + r.x + rb.x);
    o.y = tanhf(ci * (ic.y + bi.y) + co * (oc.y + bo.y) + r.y + rb.y);
    *reinterpret_cast<float2*>(h2 + (size_t)node * 64 + lane * 2) = o;
}

// ---------------- decoder: warp handles 2 nodes -----------------------------
__device__ __forceinline__ void logsm_store(float4 acc, int node, int lane,
                                            float* __restrict__ logp, int n) {
    float m = fmaxf(fmaxf(acc.x, acc.y), fmaxf(acc.z, acc.w));
#pragma unroll
    for (int off = 16; off > 0; off >>= 1)
        m = fmaxf(m, __shfl_xor_sync(0xffffffffu, m, off));
    float s = expf(acc.x - m) + expf(acc.y - m) + expf(acc.z - m) + expf(acc.w - m);
#pragma unroll
    for (int off = 16; off > 0; off >>= 1)
        s += __shfl_xor_sync(0xffffffffu, s, off);
    float lse = m + logf(s);
    if (node < n) {
        float4 o = make_float4(acc.x - lse, acc.y - lse, acc.z - lse, acc.w - lse);
        *reinterpret_cast<float4*>(logp + (size_t)node * CLS + lane * 4) = o;
    }
}

__device__ __forceinline__ void emb_store(const float* __restrict__ h, int node, int lane,
                                          float* __restrict__ emb, int n) {
    float2 v = *reinterpret_cast<const float2*>(h + lane * 2);
    float sq = v.x * v.x + v.y * v.y;
#pragma unroll
    for (int off = 16; off > 0; off >>= 1)
        sq += __shfl_xor_sync(0xffffffffu, sq, off);
    float inv = 1.f / (sqrtf(sq) + 1e-12f);
    if (node < n) {
        float2 o = make_float2(v.x * inv, v.y * inv);
        *reinterpret_cast<float2*>(emb + (size_t)node * 64 + lane * 2) = o;
    }
}

__global__ __launch_bounds__(256) void decoder_kernel(
    const float* __restrict__ h2, const float* __restrict__ W,
    const float* __restrict__ b, float* __restrict__ logp,
    float* __restrict__ emb, int n)
{
    __shared__ float sh[16 * 64];
    int tid = threadIdx.x;
    int node0 = blockIdx.x * 16;

    for (int i = tid; i < 16 * 64; i += 256) {
        int nd = node0 + (i >> 6);
        sh[i] = (nd < n) ? h2[(size_t)nd * 64 + (i & 63)] : 0.f;
    }
    __syncthreads();

    int wid = tid >> 5, lane = tid & 31;
    int la = wid * 2, lb = la + 1;
    const float* ha = sh + la * 64;
    const float* hb = sh + lb * 64;

    float4 bj = *reinterpret_cast<const float4*>(b + lane * 4);
    float4 acc0 = bj, acc1 = bj;

#pragma unroll 4
    for (int k = 0; k < 64; k++) {
        float4 w = *reinterpret_cast<const float4*>(W + (size_t)k * CLS + lane * 4);
        float a = ha[k], c = hb[k];
        acc0.x += a * w.x; acc0.y += a * w.y; acc0.z += a * w.z; acc0.w += a * w.w;
        acc1.x += c * w.x; acc1.y += c * w.y; acc1.z += c * w.z; acc1.w += c * w.w;
    }

    logsm_store(acc0, node0 + la, lane, logp, n);
    logsm_store(acc1, node0 + lb, lane, logp, n);
    emb_store(ha, node0 + la, lane, emb, n);
    emb_store(hb, node0 + lb, lane, emb, n);
}

// ---------------- host ----------------
extern "C" void kernel_launch(void* const* d_in, const int* in_sizes, int n_in,
                              void* d_out, int out_size)
{
    const float* x      = (const float*)d_in[0];
    const int*   ei_in  = (const int*)d_in[1];
    const float* ew_in  = (const float*)d_in[2];
    const int*   ei_out = (const int*)d_in[3];
    const float* ew_out = (const float*)d_in[4];
    const float* pe     = (const float*)d_in[5];

    const float* Wmi0 = (const float*)d_in[6];
    const float* Wmo0 = (const float*)d_in[7];
    const float* Ws0  = (const float*)d_in[8];
    const float* bmi0 = (const float*)d_in[9];
    const float* bmo0 = (const float*)d_in[10];
    const float* bsi0 = (const float*)d_in[11];
    const float* bso0 = (const float*)d_in[12];
    const float* cin0 = (const float*)d_in[13];
    const float* cout0= (const float*)d_in[14];

    const float* Wmi1 = (const float*)d_in[15];
    const float* Wmo1 = (const float*)d_in[16];
    const float* Ws1  = (const float*)d_in[17];
    const float* bmi1 = (const float*)d_in[18];
    const float* bmo1 = (const float*)d_in[19];
    const float* bsi1 = (const float*)d_in[20];
    const float* bso1 = (const float*)d_in[21];
    const float* cin1 = (const float*)d_in[22];
    const float* cout1= (const float*)d_in[23];

    const float* resW = (const float*)d_in[24];
    const float* resb = (const float*)d_in[25];
    const float* decW = (const float*)d_in[26];
    const float* decb = (const float*)d_in[27];

    __half *t, *u;
    float *h1, *h2, *bsum;
    float4 *blob0, *blob1;
    int *deg_in, *deg_out, *rp_in, *rp_out, *cur_in, *cur_out;
    int2 *edge_in, *edge_out;
    cudaGetSymbolAddress((void**)&t,   g_t);
    cudaGetSymbolAddress((void**)&u,   g_u);
    cudaGetSymbolAddress((void**)&h1,  g_h1);
    cudaGetSymbolAddress((void**)&h2,  g_h2);
    cudaGetSymbolAddress((void**)&blob0, g_blob0);
    cudaGetSymbolAddress((void**)&blob1, g_blob1);
    cudaGetSymbolAddress((void**)&bsum,g_bsum);
    cudaGetSymbolAddress((void**)&deg_in,  g_deg_in);
    cudaGetSymbolAddress((void**)&deg_out, g_deg_out);
    cudaGetSymbolAddress((void**)&rp_in,   g_rp_in);
    cudaGetSymbolAddress((void**)&rp_out,  g_rp_out);
    cudaGetSymbolAddress((void**)&cur_in,  g_cur_in);
    cudaGetSymbolAddress((void**)&cur_out, g_cur_out);
    cudaGetSymbolAddress((void**)&edge_in, g_edge_in);
    cudaGetSymbolAddress((void**)&edge_out,g_edge_out);

    const int N = NN, E = EE, TPB = 256;
    const int SMEM_BYTES = (128 * 132 + 2 * 16384) * 4;

    static cudaStream_t s2 = nullptr;
    static cudaEvent_t ev0 = nullptr, ev2 = nullptr;
    if (!s2) {
        cudaStreamCreateWithFlags(&s2, cudaStreamNonBlocking);
        cudaEventCreateWithFlags(&ev0, cudaEventDisableTiming);
        cudaEventCreateWithFlags(&ev2, cudaEventDisableTiming);
        cudaFuncSetAttribute((const void*)tgemm_kernel<256, true>,
                             cudaFuncAttributeMaxDynamicSharedMemorySize, SMEM_BYTES);
        cudaFuncSetAttribute((const void*)tgemm_kernel<192, false>,
                             cudaFuncAttributeMaxDynamicSharedMemorySize, SMEM_BYTES);
    }

    // fork CSR branch immediately onto s2
    cudaEventRecord(ev0, 0);
    cudaStreamWaitEvent(s2, ev0, 0);
    detect_kernel<<<(N + TPB - 1) / TPB, TPB, 0, s2>>>(ei_in, deg_in, deg_out, N);
    count_dual_kernel<<<(2 * E + TPB - 1) / TPB, TPB, 0, s2>>>(ei_in, ei_out, deg_in, deg_out, E);
    scan_kernel<<<2, 1024, 0, s2>>>(deg_in, deg_out, rp_in, rp_out, cur_in, cur_out, N);
    scatter_dual_kernel<<<(2 * E + TPB - 1) / TPB, TPB, 0, s2>>>(
        ei_in, ew_in, ei_out, ew_out, cur_in, cur_out, edge_in, edge_out, E);
    cudaEventRecord(ev2, s2);

    // main branch: weight prep + layer-0 GEMM (PE folded into A staging)
    prep_kernel<<<(16384 + 12288 + 448 + TPB - 1) / TPB, TPB>>>(
        Wmi0, Wmo0, Ws0, Wmi1, Wmo1, Ws1, resW,
        bmi0, bsi0, bmo0, bso0, bmi1, bsi1, bmo1, bso1, resb,
        blob0, blob1, bsum);

    const int GBLK = (N + 127) / 128;
    tgemm_kernel<256, true><<<GBLK, 256, SMEM_BYTES>>>(x, pe, blob0, t, N);

    // join: gather0 needs both CSR and t
    cudaStreamWaitEvent(0, ev2, 0);
    gather0_kernel<<<(N * 32 + TPB - 1) / TPB, TPB>>>(
        t, rp_in, edge_in, rp_out, edge_out,
        bsum, cin0, cout0, x, pe, h1, N);

    // layer 1
    tgemm_kernel<192, false><<<GBLK, 256, SMEM_BYTES>>>(h1, pe, blob1, u, N);
    gather1_kernel<<<(N * 32 + TPB - 1) / TPB, TPB>>>(
        u, rp_in, edge_in, rp_out, edge_out,
        bsum, cin1, cout1, h2, N);

    // decoder + log_softmax + emb
    float* out = (float*)d_out;
    decoder_kernel<<<(N + 15) / 16, 256>>>(h2, decW, decb, out, out + (size_t)N * CLS, N);
}